// round 4
// baseline (speedup 1.0000x reference)
#include <cuda_runtime.h>
#include <math.h>

#define EPS_BN 1e-5f

// ---------------- scratch (no allocations allowed) ----------------
// H: relu(bn(conv)) activations, layout [B, L, OUT] per modality
#define OFF_RGB   0
#define OFF_DEPTH 6422528      // 256*49*512
#define OFF_MM    12845056     // 2x
#define OFF_LIDAR 17039360     // + 256*32*512
__device__ float g_H[21233664];
__device__ float g_h1[32768 * 128];   // pos-enc layer1 out, [B*S, 128]
__device__ float g_newxyz[256 * 128 * 3];

// ---------------- threefry-2x32 (20 rounds) ----------------
__device__ __forceinline__ unsigned rotl32(unsigned x, int d) {
    return (x << d) | (x >> (32 - d));
}

#define TF_ROUND(x0, x1, r) do { x0 += x1; x1 = rotl32(x1, r); x1 ^= x0; } while (0)

__device__ __forceinline__ void threefry2x32(unsigned k0, unsigned k1,
                                             unsigned& x0, unsigned& x1) {
    const unsigned kx = 0x1BD11BDAu ^ k0 ^ k1;
    x0 += k0; x1 += k1;
    TF_ROUND(x0, x1, 13); TF_ROUND(x0, x1, 15); TF_ROUND(x0, x1, 26); TF_ROUND(x0, x1, 6);
    x0 += k1; x1 += kx + 1u;
    TF_ROUND(x0, x1, 17); TF_ROUND(x0, x1, 29); TF_ROUND(x0, x1, 16); TF_ROUND(x0, x1, 24);
    x0 += kx; x1 += k0 + 2u;
    TF_ROUND(x0, x1, 13); TF_ROUND(x0, x1, 15); TF_ROUND(x0, x1, 26); TF_ROUND(x0, x1, 6);
    x0 += k0; x1 += k1 + 3u;
    TF_ROUND(x0, x1, 17); TF_ROUND(x0, x1, 29); TF_ROUND(x0, x1, 16); TF_ROUND(x0, x1, 24);
    x0 += k1; x1 += kx + 4u;
    TF_ROUND(x0, x1, 13); TF_ROUND(x0, x1, 15); TF_ROUND(x0, x1, 26); TF_ROUND(x0, x1, 6);
    x0 += kx; x1 += k0 + 5u;
}

// ---------------- FPS ----------------
__global__ void fps_kernel(const float* __restrict__ pts, float* __restrict__ nxyz) {
    extern __shared__ float sh[];
    float* xs = sh;
    float* ys = sh + 4096;
    float* zs = sh + 8192;
    __shared__ float red_v[8];
    __shared__ int   red_i[8];
    __shared__ int   sm_far;

    const int b = blockIdx.x;
    const int tid = threadIdx.x;
    const float* p = pts + (size_t)b * 4096 * 3;
    for (int i = tid; i < 4096; i += 256) {
        xs[i] = p[3 * i + 0];
        ys[i] = p[3 * i + 1];
        zs[i] = p[3 * i + 2];
    }
    if (tid == 0) {
        // jax.random.randint(jax.random.key(42), (256,), 0, 4096) with
        // jax_threefry_partitionable=True (modern JAX default):
        //   k1, k2 = split(key): foldlike -> k2 = cipher((0,42), hi=0, lo=1)
        //   span = 4096 (2^12) -> multiplier = (2^16 % span)^2 % span = 0
        //   far0[b] = lower_bits[b] % span,
        //   lower_bits[b] = fold32(cipher(k2, hi=0, lo=b)) = out0 ^ out1
        unsigned a0 = 0u, a1 = 1u;
        threefry2x32(0u, 42u, a0, a1);        // a0,a1 = derived key k2
        unsigned c0 = 0u, c1 = (unsigned)b;
        threefry2x32(a0, a1, c0, c1);
        sm_far = (int)((c0 ^ c1) & 4095u);
    }
    __syncthreads();

    float dist[16];
#pragma unroll
    for (int j = 0; j < 16; j++) dist[j] = 1e10f;

    float* outp = nxyz + (size_t)b * 128 * 3;
    for (int it = 0; it < 128; ++it) {
        const int far = sm_far;
        const float cx = xs[far], cy = ys[far], cz = zs[far];
        if (tid == 0) {
            outp[3 * it + 0] = cx;
            outp[3 * it + 1] = cy;
            outp[3 * it + 2] = cz;
        }
        float bv = -1.0f;
        int bi = 0;
        // no-FMA distance (match XLA: sub, square x3, (s0+s1)+s2)
#pragma unroll
        for (int j = 0; j < 16; j++) {
            const int pi = (j << 8) + tid;
            float dx = __fadd_rn(xs[pi], -cx);
            float dy = __fadd_rn(ys[pi], -cy);
            float dz = __fadd_rn(zs[pi], -cz);
            float s0 = __fmul_rn(dx, dx);
            float s1 = __fmul_rn(dy, dy);
            float s2 = __fmul_rn(dz, dz);
            float d  = __fadd_rn(__fadd_rn(s0, s1), s2);
            float nd = fminf(dist[j], d);
            dist[j] = nd;
            if (nd > bv || (nd == bv && pi < bi)) { bv = nd; bi = pi; }
        }
        // warp argmax (first-max tie-break = lowest index)
#pragma unroll
        for (int off = 16; off > 0; off >>= 1) {
            float ov = __shfl_down_sync(0xFFFFFFFFu, bv, off);
            int   oi = __shfl_down_sync(0xFFFFFFFFu, bi, off);
            if (ov > bv || (ov == bv && oi < bi)) { bv = ov; bi = oi; }
        }
        if ((tid & 31) == 0) { red_v[tid >> 5] = bv; red_i[tid >> 5] = bi; }
        __syncthreads();
        if (tid < 8) {
            bv = red_v[tid];
            bi = red_i[tid];
#pragma unroll
            for (int off = 4; off > 0; off >>= 1) {
                float ov = __shfl_down_sync(0xFFu, bv, off);
                int   oi = __shfl_down_sync(0xFFu, bi, off);
                if (ov > bv || (ov == bv && oi < bi)) { bv = ov; bi = oi; }
            }
            if (tid == 0) sm_far = bi;
        }
        __syncthreads();
    }
}

// ---------------- tiled SGEMM with fused bias+BN+ReLU epilogue ----------------
// A: [M,K] row-major, Bm: [N,K] row-major (NT gemm)
// C[r,c] = relu( (sum_k A[r,k]*Bm[c,k] + bias[c] - m[c]) * g[c]/sqrt(v[c]+eps) + bnb[c] )
// addmode=1 -> C += value
__global__ __launch_bounds__(256) void sgemm_bn(
    const float* __restrict__ A, const float* __restrict__ Bm,
    float* __restrict__ C, int M, int N, int K,
    const float* __restrict__ bias,
    const float* __restrict__ bng, const float* __restrict__ bnb,
    const float* __restrict__ bnm, const float* __restrict__ bnv,
    int addmode)
{
    __shared__ float As[16][128];
    __shared__ float Bs[16][128];
    const int tid = threadIdx.x;
    const int m0 = blockIdx.y * 128;
    const int n0 = blockIdx.x * 128;
    const float* Ab = A + (size_t)m0 * K;
    const float* Bb = Bm + (size_t)n0 * K;
    const int tx = tid & 15, ty = tid >> 4;

    float acc[8][8];
#pragma unroll
    for (int i = 0; i < 8; i++)
#pragma unroll
        for (int j = 0; j < 8; j++) acc[i][j] = 0.0f;

    for (int k0 = 0; k0 < K; k0 += 16) {
#pragma unroll
        for (int rep = 0; rep < 2; rep++) {
            int t = tid + rep * 256;
            int r = t >> 2;
            int c4 = (t & 3) << 2;
            float4 av = *(const float4*)(Ab + (size_t)r * K + k0 + c4);
            As[c4 + 0][r] = av.x; As[c4 + 1][r] = av.y;
            As[c4 + 2][r] = av.z; As[c4 + 3][r] = av.w;
            float4 bv = *(const float4*)(Bb + (size_t)r * K + k0 + c4);
            Bs[c4 + 0][r] = bv.x; Bs[c4 + 1][r] = bv.y;
            Bs[c4 + 2][r] = bv.z; Bs[c4 + 3][r] = bv.w;
        }
        __syncthreads();
#pragma unroll
        for (int kk = 0; kk < 16; kk++) {
            float af[8], bf[8];
#pragma unroll
            for (int i = 0; i < 8; i++) af[i] = As[kk][ty * 8 + i];
#pragma unroll
            for (int j = 0; j < 8; j++) bf[j] = Bs[kk][tx * 8 + j];
#pragma unroll
            for (int i = 0; i < 8; i++)
#pragma unroll
                for (int j = 0; j < 8; j++) acc[i][j] += af[i] * bf[j];
        }
        __syncthreads();
    }

    float alpha[8], beta[8];
#pragma unroll
    for (int j = 0; j < 8; j++) {
        int c = n0 + tx * 8 + j;
        float s = bng[c] / sqrtf(bnv[c] + EPS_BN);
        alpha[j] = s;
        beta[j] = (bias[c] - bnm[c]) * s + bnb[c];
    }
#pragma unroll
    for (int i = 0; i < 8; i++) {
        int r = m0 + ty * 8 + i;
        float* crow = C + (size_t)r * N + n0 + tx * 8;
#pragma unroll
        for (int j = 0; j < 8; j++) {
            float v = fmaxf(acc[i][j] * alpha[j] + beta[j], 0.0f);
            if (addmode) crow[j] += v;
            else         crow[j] = v;
        }
    }
}

// ---------------- token-mix linear (L -> 32) + ReLU, writes proj into out ----------------
__global__ void mix_kernel(
    const float* __restrict__ lin_w_img, const float* __restrict__ lin_b_img,
    const float* __restrict__ lin_w_pc,  const float* __restrict__ lin_b_pc,
    float* __restrict__ out)
{
    __shared__ float lw[32 * 49];
    __shared__ float lb[32];
    __shared__ float smH[49 * 32];

    const int o0 = blockIdx.x * 32;
    const int b = blockIdx.y;
    const int mod = blockIdx.z;
    const int tid = threadIdx.x;
    const int Lm = (mod < 2) ? 49 : 32;

    const float* wsrc = (mod == 0) ? lin_w_img
                      : (mod == 1) ? lin_w_img + 32 * 49
                      : (mod == 2) ? lin_w_pc
                                   : lin_w_pc + 32 * 32;
    const float* bsrc = (mod == 0) ? lin_b_img
                      : (mod == 1) ? lin_b_img + 32
                      : (mod == 2) ? lin_b_pc
                                   : lin_b_pc + 32;
    size_t Hoff = (mod == 0) ? (size_t)OFF_RGB
                : (mod == 1) ? (size_t)OFF_DEPTH
                : (mod == 2) ? (size_t)OFF_MM
                             : (size_t)OFF_LIDAR;
    const float* Hb = g_H + Hoff + (size_t)b * Lm * 512;

    for (int i = tid; i < 32 * Lm; i += 256) lw[i] = wsrc[i];
    if (tid < 32) lb[tid] = bsrc[tid];
    for (int i = tid; i < Lm * 32; i += 256) {
        int l = i >> 5, o = i & 31;
        smH[i] = Hb[(size_t)l * 512 + o0 + o];
    }
    __syncthreads();

#pragma unroll
    for (int p = 0; p < 4; p++) {
        int lin = tid + (p << 8);
        int k = lin >> 5, o = lin & 31;
        float acc = lb[k];
        for (int l = 0; l < Lm; l++) acc += smH[l * 32 + o] * lw[k * Lm + l];
        acc = fmaxf(acc, 0.0f);
        out[((size_t)b * 128 + mod * 32 + k) * 512 + o0 + o] = acc;
    }
}

// ---------------- pos-enc layer1: 3 -> 128, BN, ReLU ----------------
__global__ void pe1_kernel(
    const float* __restrict__ w1, const float* __restrict__ b1,
    const float* __restrict__ g1, const float* __restrict__ bb1,
    const float* __restrict__ m1, const float* __restrict__ v1)
{
    int idx = blockIdx.x * 256 + threadIdx.x;   // < 32768*128
    int row = idx >> 7, c = idx & 127;
    const float* xyz = g_newxyz + (size_t)row * 3;
    float x = xyz[0], y = xyz[1], z = xyz[2];
    float acc = w1[c * 3 + 0] * x + w1[c * 3 + 1] * y + w1[c * 3 + 2] * z + b1[c];
    float s = g1[c] / sqrtf(v1[c] + EPS_BN);
    g_h1[idx] = fmaxf((acc - m1[c]) * s + bb1[c], 0.0f);
}

// ---------------- launch ----------------
extern "C" void kernel_launch(void* const* d_in, const int* in_sizes, int n_in,
                              void* d_out, int out_size) {
    (void)in_sizes; (void)n_in; (void)out_size;
    const float* rgb       = (const float*)d_in[0];
    const float* depth     = (const float*)d_in[1];
    const float* mmwave    = (const float*)d_in[2];
    const float* lidar     = (const float*)d_in[3];
    const float* pts       = (const float*)d_in[4];
    const float* conv_w    = (const float*)d_in[5];
    const float* conv_b    = (const float*)d_in[6];
    const float* bn_g      = (const float*)d_in[7];
    const float* bn_b      = (const float*)d_in[8];
    const float* bn_m      = (const float*)d_in[9];
    const float* bn_v      = (const float*)d_in[10];
    const float* lin_w_img = (const float*)d_in[11];
    const float* lin_b_img = (const float*)d_in[12];
    const float* lin_w_pc  = (const float*)d_in[13];
    const float* lin_b_pc  = (const float*)d_in[14];
    const float* pe_w1     = (const float*)d_in[15];
    const float* pe_b1     = (const float*)d_in[16];
    const float* pe_g1     = (const float*)d_in[17];
    const float* pe_bb1    = (const float*)d_in[18];
    const float* pe_m1     = (const float*)d_in[19];
    const float* pe_v1     = (const float*)d_in[20];
    const float* pe_w2     = (const float*)d_in[21];
    const float* pe_b2     = (const float*)d_in[22];
    const float* pe_g2     = (const float*)d_in[23];
    const float* pe_bb2    = (const float*)d_in[24];
    const float* pe_m2     = (const float*)d_in[25];
    const float* pe_v2     = (const float*)d_in[26];
    float* out = (float*)d_out;

    float *H, *h1, *nx;
    cudaGetSymbolAddress((void**)&H,  g_H);
    cudaGetSymbolAddress((void**)&h1, g_h1);
    cudaGetSymbolAddress((void**)&nx, g_newxyz);

    cudaFuncSetAttribute(fps_kernel, cudaFuncAttributeMaxDynamicSharedMemorySize, 50176);

    // FPS (independent of branches) -> new_xyz
    fps_kernel<<<256, 256, 49152>>>(pts, nx);

    // 4 branch GEMMs: X[B*L,512] x conv_w[mod]^T -> H (bn+relu fused)
    sgemm_bn<<<dim3(4, 98), 256>>>(rgb,    conv_w + 0 * 262144, H + OFF_RGB,   12544, 512, 512,
                                   conv_b + 0,    bn_g + 0,    bn_b + 0,    bn_m + 0,    bn_v + 0,    0);
    sgemm_bn<<<dim3(4, 98), 256>>>(depth,  conv_w + 1 * 262144, H + OFF_DEPTH, 12544, 512, 512,
                                   conv_b + 512,  bn_g + 512,  bn_b + 512,  bn_m + 512,  bn_v + 512,  0);
    sgemm_bn<<<dim3(4, 64), 256>>>(mmwave, conv_w + 2 * 262144, H + OFF_MM,    8192,  512, 512,
                                   conv_b + 1024, bn_g + 1024, bn_b + 1024, bn_m + 1024, bn_v + 1024, 0);
    sgemm_bn<<<dim3(4, 64), 256>>>(lidar,  conv_w + 3 * 262144, H + OFF_LIDAR, 8192,  512, 512,
                                   conv_b + 1536, bn_g + 1536, bn_b + 1536, bn_m + 1536, bn_v + 1536, 0);

    // token mix -> writes every element of out (proj)
    mix_kernel<<<dim3(16, 256, 4), 256>>>(lin_w_img, lin_b_img, lin_w_pc, lin_b_pc, out);

    // pos-enc layer1 (needs FPS result)
    pe1_kernel<<<16384, 256>>>(pe_w1, pe_b1, pe_g1, pe_bb1, pe_m1, pe_v1);

    // pos-enc layer2 GEMM, bn+relu, accumulated into out
    sgemm_bn<<<dim3(4, 256), 256>>>(h1, pe_w2, out, 32768, 512, 128,
                                    pe_b2, pe_g2, pe_bb2, pe_m2, pe_v2, 1);
}

// round 7
// speedup vs baseline: 1.5699x; 1.5699x over previous
#include <cuda_runtime.h>
#include <cuda_bf16.h>
#include <math.h>
#include <stdint.h>

#define EPS_BN 1e-5f

// ---------------- scratch ----------------
#define OFF_RGB   0
#define OFF_DEPTH 6422528      // 256*49*512
#define OFF_MM    12845056
#define OFF_LIDAR 17039360
__device__ float g_H[21233664];
__device__ float g_h1[32768 * 128];   // pos-enc layer1 out, [B*S, 128]
__device__ float g_newxyz[256 * 128 * 3];

// ---------------- helpers ----------------
__device__ __forceinline__ uint32_t smem_u32(const void* p) {
    uint32_t a;
    asm("{ .reg .u64 t; cvta.to.shared.u64 t, %1; cvt.u32.u64 %0, t; }" : "=r"(a) : "l"(p));
    return a;
}

__device__ __forceinline__ void mma_bf16(float* c, const uint32_t* a, const uint32_t* b) {
    asm volatile(
        "mma.sync.aligned.m16n8k16.row.col.f32.bf16.bf16.f32 "
        "{%0,%1,%2,%3}, {%4,%5,%6,%7}, {%8,%9}, {%0,%1,%2,%3};"
        : "+f"(c[0]), "+f"(c[1]), "+f"(c[2]), "+f"(c[3])
        : "r"(a[0]), "r"(a[1]), "r"(a[2]), "r"(a[3]), "r"(b[0]), "r"(b[1]));
}

#define LDSM_X4(r0, r1, r2, r3, addr)                                        \
    asm volatile("ldmatrix.sync.aligned.m8n8.x4.shared.b16 {%0,%1,%2,%3}, [%4];" \
                 : "=r"(r0), "=r"(r1), "=r"(r2), "=r"(r3) : "r"(addr))
#define LDSM_X2(r0, r1, addr)                                                \
    asm volatile("ldmatrix.sync.aligned.m8n8.x2.shared.b16 {%0,%1}, [%2];"   \
                 : "=r"(r0), "=r"(r1) : "r"(addr))

// tile geometry: 128 rows x 64 bf16 cols = 128 B/row = 16384 B per tile
#define TILE_BYTES 16384
#define STAGE_BYTES 65536          // AH, AL, BH, BL
#define GEMM_SMEM (2 * STAGE_BYTES)

// convert fp32 pair -> bf16 hi/lo split, store into swizzled smem
// swizzle: 16B-chunk index ^= (r&7)
__device__ __forceinline__ void cvt_store(char* baseH, char* baseL, int r, int c,
                                          float x, float y) {
    uint32_t hi;
    asm("cvt.rn.bf16x2.f32 %0, %1, %2;" : "=r"(hi) : "f"(y), "f"(x));
    __nv_bfloat162 h2 = *(__nv_bfloat162*)&hi;
    float rx = x - __bfloat162float(h2.x);
    float ry = y - __bfloat162float(h2.y);
    uint32_t lo;
    asm("cvt.rn.bf16x2.f32 %0, %1, %2;" : "=r"(lo) : "f"(ry), "f"(rx));
    uint32_t off = (uint32_t)(r * 128 + ((((c >> 3) ^ (r & 7)) << 4)) + ((c & 7) << 1));
    *(uint32_t*)(baseH + off) = hi;
    *(uint32_t*)(baseL + off) = lo;
}

// ---------------- bf16-split HMMA GEMM with fused bias+BN+ReLU ----------------
// C[m, n0..n0+128) = relu((sum_k A[m,k]*Bm[n,k] + bias[n] - bnm[n]) * bng[n]*rsqrt(bnv[n]+eps) + bnb[n])
// A: [M,K] row-major, Bm: [N,K] row-major. CTA tile 128x128, K chunk 64, K%64==0, M%128==0.
__global__ __launch_bounds__(256, 1)
void hmma_gemm(const float* __restrict__ A, const float* __restrict__ Bm,
               float* __restrict__ C, int Nld, int K,
               const float* __restrict__ bias,
               const float* __restrict__ bng, const float* __restrict__ bnb,
               const float* __restrict__ bnm, const float* __restrict__ bnv,
               int addmode)
{
    extern __shared__ char smem[];           // 2 stages x 65536
    __shared__ float s_alpha[128], s_beta[128];

    const int tid = threadIdx.x;
    const int wid = tid >> 5;
    const int lane = tid & 31;
    const int n0 = blockIdx.x * 128;
    const int m0 = blockIdx.y * 128;
    const int warp_m = wid >> 2;             // 0..1
    const int warp_n = wid & 3;              // 0..3

    if (tid < 128) {
        int c = n0 + tid;
        float s = bng[c] * rsqrtf(bnv[c] + EPS_BN);
        s_alpha[tid] = s;
        s_beta[tid]  = (bias[c] - bnm[c]) * s + bnb[c];
    }

    const int kn = K >> 6;
    float acc[4][4][4];
#pragma unroll
    for (int i = 0; i < 4; i++)
#pragma unroll
        for (int j = 0; j < 4; j++)
#pragma unroll
            for (int q = 0; q < 4; q++) acc[i][j][q] = 0.0f;

    const int r0 = tid >> 2;                 // 0..63
    const int cb = (tid & 3) * 2;            // 0,2,4,6

    float2 ra[16], rb[16];

    // ---- load chunk regs ----
#define LOAD_CHUNK(ck) do {                                                   \
        const int k0 = (ck) << 6;                                             \
        _Pragma("unroll")                                                     \
        for (int pass = 0; pass < 2; pass++) {                                \
            const int r = r0 + 64 * pass;                                     \
            const float* arow = A + (size_t)(m0 + r) * K + k0;                \
            const float* brow = Bm + (size_t)(n0 + r) * K + k0;               \
            _Pragma("unroll")                                                 \
            for (int j = 0; j < 8; j++) {                                     \
                ra[pass * 8 + j] = *(const float2*)(arow + cb + 8 * j);       \
                rb[pass * 8 + j] = *(const float2*)(brow + cb + 8 * j);       \
            }                                                                 \
        }                                                                     \
    } while (0)

    // ---- convert + store regs into stage st ----
#define STORE_CHUNK(st) do {                                                  \
        char* AH = smem + (st) * STAGE_BYTES;                                 \
        char* AL = AH + TILE_BYTES;                                           \
        char* BH = AH + 2 * TILE_BYTES;                                       \
        char* BL = AH + 3 * TILE_BYTES;                                       \
        _Pragma("unroll")                                                     \
        for (int pass = 0; pass < 2; pass++) {                                \
            const int r = r0 + 64 * pass;                                     \
            _Pragma("unroll")                                                 \
            for (int j = 0; j < 8; j++) {                                     \
                const int c = cb + 8 * j;                                     \
                float2 av = ra[pass * 8 + j];                                 \
                cvt_store(AH, AL, r, c, av.x, av.y);                          \
                float2 bv = rb[pass * 8 + j];                                 \
                cvt_store(BH, BL, r, c, bv.x, bv.y);                          \
            }                                                                 \
        }                                                                     \
    } while (0)

    // prologue
    LOAD_CHUNK(0);
    STORE_CHUNK(0);
    __syncthreads();

    const uint32_t sb0 = smem_u32(smem);

    for (int ck = 0; ck < kn; ck++) {
        if (ck + 1 < kn) LOAD_CHUNK(ck + 1);

        // ---- MMA phase on stage ck&1 ----
        {
            const uint32_t sbase = sb0 + (ck & 1) * STAGE_BYTES;
            // A lane addressing (ldmatrix x4: lanes 0-15 k-half 0, 16-31 k-half 1)
            const int arow = warp_m * 64 + (lane & 15);          // + mt*16
            const int ahalf = lane >> 4;
            // B lane addressing (ldmatrix x2: lanes 0-7 k-half 0, 8-15 k-half 1)
            const int bn_ = warp_n * 32 + (lane & 7);            // + nt*8
            const int bhalf = (lane >> 3) & 1;

#pragma unroll
            for (int kb = 0; kb < 4; kb++) {
                uint32_t aH[4][4], aL[4][4], bH[4][2], bL[4][2];
#pragma unroll
                for (int mt = 0; mt < 4; mt++) {
                    const int r = arow + mt * 16;
                    const uint32_t chunk = (uint32_t)((2 * kb + ahalf) ^ (r & 7));
                    const uint32_t ad = sbase + (uint32_t)(r * 128) + chunk * 16;
                    LDSM_X4(aH[mt][0], aH[mt][1], aH[mt][2], aH[mt][3], ad);
                    LDSM_X4(aL[mt][0], aL[mt][1], aL[mt][2], aL[mt][3], ad + TILE_BYTES);
                }
#pragma unroll
                for (int nt = 0; nt < 4; nt++) {
                    const int n = bn_ + nt * 8;
                    const uint32_t chunk = (uint32_t)((2 * kb + bhalf) ^ (n & 7));
                    const uint32_t bd = sbase + 2u * TILE_BYTES + (uint32_t)(n * 128) + chunk * 16;
                    LDSM_X2(bH[nt][0], bH[nt][1], bd);
                    LDSM_X2(bL[nt][0], bL[nt][1], bd + TILE_BYTES);
                }
#pragma unroll
                for (int mt = 0; mt < 4; mt++)
#pragma unroll
                    for (int nt = 0; nt < 4; nt++) {
                        mma_bf16(acc[mt][nt], aH[mt], bH[nt]);
                        mma_bf16(acc[mt][nt], aH[mt], bL[nt]);
                        mma_bf16(acc[mt][nt], aL[mt], bH[nt]);
                    }
            }
        }

        if (ck + 1 < kn) STORE_CHUNK((ck + 1) & 1);
        __syncthreads();
    }

    // ---- epilogue ----
    const int erow = (lane >> 2);
    const int ecol = 2 * (lane & 3);
#pragma unroll
    for (int mt = 0; mt < 4; mt++) {
#pragma unroll
        for (int nt = 0; nt < 4; nt++) {
            const int lc = warp_n * 32 + nt * 8 + ecol;
            const float a0 = s_alpha[lc], a1 = s_alpha[lc + 1];
            const float b0 = s_beta[lc],  b1 = s_beta[lc + 1];
            const int gr0 = m0 + warp_m * 64 + mt * 16 + erow;
            float* p0 = C + (size_t)gr0 * Nld + n0 + lc;
            float* p1 = p0 + (size_t)8 * Nld;
            float2 v0, v1;
            v0.x = fmaxf(fmaf(acc[mt][nt][0], a0, b0), 0.0f);
            v0.y = fmaxf(fmaf(acc[mt][nt][1], a1, b1), 0.0f);
            v1.x = fmaxf(fmaf(acc[mt][nt][2], a0, b0), 0.0f);
            v1.y = fmaxf(fmaf(acc[mt][nt][3], a1, b1), 0.0f);
            if (addmode) {
                float2 o0 = *(float2*)p0;
                float2 o1 = *(float2*)p1;
                v0.x += o0.x; v0.y += o0.y;
                v1.x += o1.x; v1.y += o1.y;
            }
            *(float2*)p0 = v0;
            *(float2*)p1 = v1;
        }
    }
#undef LOAD_CHUNK
#undef STORE_CHUNK
}

// ---------------- threefry-2x32 ----------------
__device__ __forceinline__ unsigned rotl32(unsigned x, int d) {
    return (x << d) | (x >> (32 - d));
}
#define TF_ROUND(x0, x1, r) do { x0 += x1; x1 = rotl32(x1, r); x1 ^= x0; } while (0)
__device__ __forceinline__ void threefry2x32(unsigned k0, unsigned k1,
                                             unsigned& x0, unsigned& x1) {
    const unsigned kx = 0x1BD11BDAu ^ k0 ^ k1;
    x0 += k0; x1 += k1;
    TF_ROUND(x0, x1, 13); TF_ROUND(x0, x1, 15); TF_ROUND(x0, x1, 26); TF_ROUND(x0, x1, 6);
    x0 += k1; x1 += kx + 1u;
    TF_ROUND(x0, x1, 17); TF_ROUND(x0, x1, 29); TF_ROUND(x0, x1, 16); TF_ROUND(x0, x1, 24);
    x0 += kx; x1 += k0 + 2u;
    TF_ROUND(x0, x1, 13); TF_ROUND(x0, x1, 15); TF_ROUND(x0, x1, 26); TF_ROUND(x0, x1, 6);
    x0 += k0; x1 += k1 + 3u;
    TF_ROUND(x0, x1, 17); TF_ROUND(x0, x1, 29); TF_ROUND(x0, x1, 16); TF_ROUND(x0, x1, 24);
    x0 += k1; x1 += kx + 4u;
    TF_ROUND(x0, x1, 13); TF_ROUND(x0, x1, 15); TF_ROUND(x0, x1, 26); TF_ROUND(x0, x1, 6);
    x0 += kx; x1 += k0 + 5u;
}

// ---------------- FPS ----------------
__global__ void fps_kernel(const float* __restrict__ pts, float* __restrict__ nxyz) {
    extern __shared__ float sh[];
    float* xs = sh;
    float* ys = sh + 4096;
    float* zs = sh + 8192;
    __shared__ float red_v[8];
    __shared__ int   red_i[8];
    __shared__ int   sm_far;

    const int b = blockIdx.x;
    const int tid = threadIdx.x;
    const float* p = pts + (size_t)b * 4096 * 3;
    for (int i = tid; i < 4096; i += 256) {
        xs[i] = p[3 * i + 0];
        ys[i] = p[3 * i + 1];
        zs[i] = p[3 * i + 2];
    }
    if (tid == 0) {
        unsigned a0 = 0u, a1 = 1u;
        threefry2x32(0u, 42u, a0, a1);        // derived key k2
        unsigned c0 = 0u, c1 = (unsigned)b;
        threefry2x32(a0, a1, c0, c1);
        sm_far = (int)((c0 ^ c1) & 4095u);
    }
    __syncthreads();

    float dist[16];
#pragma unroll
    for (int j = 0; j < 16; j++) dist[j] = 1e10f;

    float* outp = nxyz + (size_t)b * 128 * 3;
    for (int it = 0; it < 128; ++it) {
        const int far = sm_far;
        const float cx = xs[far], cy = ys[far], cz = zs[far];
        if (tid == 0) {
            outp[3 * it + 0] = cx;
            outp[3 * it + 1] = cy;
            outp[3 * it + 2] = cz;
        }
        float bv = -1.0f;
        int bi = 0;
#pragma unroll
        for (int j = 0; j < 16; j++) {
            const int pi = (j << 8) + tid;
            float dx = __fadd_rn(xs[pi], -cx);
            float dy = __fadd_rn(ys[pi], -cy);
            float dz = __fadd_rn(zs[pi], -cz);
            float s0 = __fmul_rn(dx, dx);
            float s1 = __fmul_rn(dy, dy);
            float s2 = __fmul_rn(dz, dz);
            float d  = __fadd_rn(__fadd_rn(s0, s1), s2);
            float nd = fminf(dist[j], d);
            dist[j] = nd;
            if (nd > bv || (nd == bv && pi < bi)) { bv = nd; bi = pi; }
        }
#pragma unroll
        for (int off = 16; off > 0; off >>= 1) {
            float ov = __shfl_down_sync(0xFFFFFFFFu, bv, off);
            int   oi = __shfl_down_sync(0xFFFFFFFFu, bi, off);
            if (ov > bv || (ov == bv && oi < bi)) { bv = ov; bi = oi; }
        }
        if ((tid & 31) == 0) { red_v[tid >> 5] = bv; red_i[tid >> 5] = bi; }
        __syncthreads();
        if (tid < 8) {
            bv = red_v[tid];
            bi = red_i[tid];
#pragma unroll
            for (int off = 4; off > 0; off >>= 1) {
                float ov = __shfl_down_sync(0xFFu, bv, off);
                int   oi = __shfl_down_sync(0xFFu, bi, off);
                if (ov > bv || (ov == bv && oi < bi)) { bv = ov; bi = oi; }
            }
            if (tid == 0) sm_far = bi;
        }
        __syncthreads();
    }
}

// ---------------- token-mix linear (L -> 32) + ReLU ----------------
__global__ void mix_kernel(
    const float* __restrict__ lin_w_img, const float* __restrict__ lin_b_img,
    const float* __restrict__ lin_w_pc,  const float* __restrict__ lin_b_pc,
    float* __restrict__ out)
{
    __shared__ float lw[32 * 49];
    __shared__ float lb[32];
    __shared__ float smH[49 * 32];

    const int o0 = blockIdx.x * 32;
    const int b = blockIdx.y;
    const int mod = blockIdx.z;
    const int tid = threadIdx.x;
    const int Lm = (mod < 2) ? 49 : 32;

    const float* wsrc = (mod == 0) ? lin_w_img
                      : (mod == 1) ? lin_w_img + 32 * 49
                      : (mod == 2) ? lin_w_pc
                                   : lin_w_pc + 32 * 32;
    const float* bsrc = (mod == 0) ? lin_b_img
                      : (mod == 1) ? lin_b_img + 32
                      : (mod == 2) ? lin_b_pc
                                   : lin_b_pc + 32;
    size_t Hoff = (mod == 0) ? (size_t)OFF_RGB
                : (mod == 1) ? (size_t)OFF_DEPTH
                : (mod == 2) ? (size_t)OFF_MM
                             : (size_t)OFF_LIDAR;
    const float* Hb = g_H + Hoff + (size_t)b * Lm * 512;

    for (int i = tid; i < 32 * Lm; i += 256) lw[i] = wsrc[i];
    if (tid < 32) lb[tid] = bsrc[tid];
    for (int i = tid; i < Lm * 32; i += 256) {
        int l = i >> 5, o = i & 31;
        smH[i] = Hb[(size_t)l * 512 + o0 + o];
    }
    __syncthreads();

#pragma unroll
    for (int p = 0; p < 4; p++) {
        int lin = tid + (p << 8);
        int k = lin >> 5, o = lin & 31;
        float acc = lb[k];
        for (int l = 0; l < Lm; l++) acc += smH[l * 32 + o] * lw[k * Lm + l];
        acc = fmaxf(acc, 0.0f);
        out[((size_t)b * 128 + mod * 32 + k) * 512 + o0 + o] = acc;
    }
}

// ---------------- pos-enc layer1: 3 -> 128, BN, ReLU ----------------
__global__ void pe1_kernel(
    const float* __restrict__ w1, const float* __restrict__ b1,
    const float* __restrict__ g1, const float* __restrict__ bb1,
    const float* __restrict__ m1, const float* __restrict__ v1)
{
    int idx = blockIdx.x * 256 + threadIdx.x;
    int row = idx >> 7, c = idx & 127;
    const float* xyz = g_newxyz + (size_t)row * 3;
    float x = xyz[0], y = xyz[1], z = xyz[2];
    float acc = w1[c * 3 + 0] * x + w1[c * 3 + 1] * y + w1[c * 3 + 2] * z + b1[c];
    float s = g1[c] / sqrtf(v1[c] + EPS_BN);
    g_h1[idx] = fmaxf((acc - m1[c]) * s + bb1[c], 0.0f);
}

// ---------------- launch ----------------
extern "C" void kernel_launch(void* const* d_in, const int* in_sizes, int n_in,
                              void* d_out, int out_size) {
    (void)in_sizes; (void)n_in; (void)out_size;
    const float* rgb       = (const float*)d_in[0];
    const float* depth     = (const float*)d_in[1];
    const float* mmwave    = (const float*)d_in[2];
    const float* lidar     = (const float*)d_in[3];
    const float* pts       = (const float*)d_in[4];
    const float* conv_w    = (const float*)d_in[5];
    const float* conv_b    = (const float*)d_in[6];
    const float* bn_g      = (const float*)d_in[7];
    const float* bn_b      = (const float*)d_in[8];
    const float* bn_m      = (const float*)d_in[9];
    const float* bn_v      = (const float*)d_in[10];
    const float* lin_w_img = (const float*)d_in[11];
    const float* lin_b_img = (const float*)d_in[12];
    const float* lin_w_pc  = (const float*)d_in[13];
    const float* lin_b_pc  = (const float*)d_in[14];
    const float* pe_w1     = (const float*)d_in[15];
    const float* pe_b1     = (const float*)d_in[16];
    const float* pe_g1     = (const float*)d_in[17];
    const float* pe_bb1    = (const float*)d_in[18];
    const float* pe_m1     = (const float*)d_in[19];
    const float* pe_v1     = (const float*)d_in[20];
    const float* pe_w2     = (const float*)d_in[21];
    const float* pe_b2     = (const float*)d_in[22];
    const float* pe_g2     = (const float*)d_in[23];
    const float* pe_bb2    = (const float*)d_in[24];
    const float* pe_m2     = (const float*)d_in[25];
    const float* pe_v2     = (const float*)d_in[26];
    float* out = (float*)d_out;

    float *H, *h1, *nx;
    cudaGetSymbolAddress((void**)&H,  g_H);
    cudaGetSymbolAddress((void**)&h1, g_h1);
    cudaGetSymbolAddress((void**)&nx, g_newxyz);

    cudaFuncSetAttribute(fps_kernel, cudaFuncAttributeMaxDynamicSharedMemorySize, 50176);
    cudaFuncSetAttribute(hmma_gemm, cudaFuncAttributeMaxDynamicSharedMemorySize, GEMM_SMEM);

    // FPS -> new_xyz
    fps_kernel<<<256, 256, 49152>>>(pts, nx);

    // 4 branch GEMMs (bf16-split HMMA): H = relu(bn(X @ W^T + b))
    hmma_gemm<<<dim3(4, 98), 256, GEMM_SMEM>>>(rgb,    conv_w + 0 * 262144, H + OFF_RGB,   512, 512,
        conv_b + 0,    bn_g + 0,    bn_b + 0,    bn_m + 0,    bn_v + 0,    0);
    hmma_gemm<<<dim3(4, 98), 256, GEMM_SMEM>>>(depth,  conv_w + 1 * 262144, H + OFF_DEPTH, 512, 512,
        conv_b + 512,  bn_g + 512,  bn_b + 512,  bn_m + 512,  bn_v + 512,  0);
    hmma_gemm<<<dim3(4, 64), 256, GEMM_SMEM>>>(mmwave, conv_w + 2 * 262144, H + OFF_MM,    512, 512,
        conv_b + 1024, bn_g + 1024, bn_b + 1024, bn_m + 1024, bn_v + 1024, 0);
    hmma_gemm<<<dim3(4, 64), 256, GEMM_SMEM>>>(lidar,  conv_w + 3 * 262144, H + OFF_LIDAR, 512, 512,
        conv_b + 1536, bn_g + 1536, bn_b + 1536, bn_m + 1536, bn_v + 1536, 0);

    // token mix -> writes all of out (proj)
    mix_kernel<<<dim3(16, 256, 4), 256>>>(lin_w_img, lin_b_img, lin_w_pc, lin_b_pc, out);

    // pos-enc layer1 (needs FPS result)
    pe1_kernel<<<16384, 256>>>(pe_w1, pe_b1, pe_g1, pe_bb1, pe_m1, pe_v1);

    // pos-enc layer2 GEMM, bn+relu, accumulated into out
    hmma_gemm<<<dim3(4, 256), 256, GEMM_SMEM>>>(h1, pe_w2, out, 512, 128,
        pe_b2, pe_g2, pe_bb2, pe_m2, pe_v2, 1);
}

// round 8
// speedup vs baseline: 2.0761x; 1.3224x over previous
#include <cuda_runtime.h>
#include <cuda_bf16.h>
#include <math.h>
#include <stdint.h>

#define EPS_BN 1e-5f

// ---------------- scratch ----------------
#define OFF_RGB   0
#define OFF_DEPTH 6422528      // 256*49*512
#define OFF_MM    12845056
#define OFF_LIDAR 17039360
__device__ float g_H[21233664];
__device__ float g_h1[32768 * 128];   // pos-enc layer1 out, [B*S, 128]
__device__ float g_newxyz[256 * 128 * 3];

// ---------------- helpers ----------------
__device__ __forceinline__ uint32_t smem_u32(const void* p) {
    uint32_t a;
    asm("{ .reg .u64 t; cvta.to.shared.u64 t, %1; cvt.u32.u64 %0, t; }" : "=r"(a) : "l"(p));
    return a;
}

__device__ __forceinline__ void mma_bf16(float* c, const uint32_t* a, const uint32_t* b) {
    asm volatile(
        "mma.sync.aligned.m16n8k16.row.col.f32.bf16.bf16.f32 "
        "{%0,%1,%2,%3}, {%4,%5,%6,%7}, {%8,%9}, {%0,%1,%2,%3};"
        : "+f"(c[0]), "+f"(c[1]), "+f"(c[2]), "+f"(c[3])
        : "r"(a[0]), "r"(a[1]), "r"(a[2]), "r"(a[3]), "r"(b[0]), "r"(b[1]));
}

#define LDSM_X4(r0, r1, r2, r3, addr)                                        \
    asm volatile("ldmatrix.sync.aligned.m8n8.x4.shared.b16 {%0,%1,%2,%3}, [%4];" \
                 : "=r"(r0), "=r"(r1), "=r"(r2), "=r"(r3) : "r"(addr))
#define LDSM_X2(r0, r1, addr)                                                \
    asm volatile("ldmatrix.sync.aligned.m8n8.x2.shared.b16 {%0,%1}, [%2];"   \
                 : "=r"(r0), "=r"(r1) : "r"(addr))

// tile geometry: 128 rows x 64 bf16 cols = 128 B/row = 16384 B per tile
#define TILE_BYTES 16384
#define GEMM_SMEM (4 * TILE_BYTES)      // AH, AL, BH, BL (single stage)

__device__ __forceinline__ uint32_t pack_bf16x2(float x, float y) {
    uint32_t h;
    asm("cvt.rn.bf16x2.f32 %0, %1, %2;" : "=r"(h) : "f"(y), "f"(x));
    return h;
}
__device__ __forceinline__ void split2(float x, float y, uint32_t& hi, uint32_t& lo) {
    hi = pack_bf16x2(x, y);
    __nv_bfloat162 h2 = *(__nv_bfloat162*)&hi;
    lo = pack_bf16x2(x - __bfloat162float(h2.x), y - __bfloat162float(h2.y));
}

// 8 consecutive fp32 cols -> hi/lo bf16 16B chunks, swizzled store
__device__ __forceinline__ void cvt8_store(char* baseH, char* baseL, int r, int g,
                                           float4 v0, float4 v1) {
    uint4 hi, lo;
    split2(v0.x, v0.y, hi.x, lo.x);
    split2(v0.z, v0.w, hi.y, lo.y);
    split2(v1.x, v1.y, hi.z, lo.z);
    split2(v1.z, v1.w, hi.w, lo.w);
    uint32_t off = (uint32_t)(r * 128 + ((g ^ (r & 7)) << 4));
    *(uint4*)(baseH + off) = hi;
    *(uint4*)(baseL + off) = lo;
}

// ---------------- bf16-split HMMA GEMM core, fused bias+BN+ReLU ----------------
__device__ __forceinline__ void gemm_core(
    const float* __restrict__ A, const float* __restrict__ Bm,
    float* __restrict__ C, int Nld, int K,
    const float* __restrict__ bias,
    const float* __restrict__ bng, const float* __restrict__ bnb,
    const float* __restrict__ bnm, const float* __restrict__ bnv,
    int addmode, int m0, int n0)
{
    extern __shared__ char smem[];       // single stage: AH AL BH BL
    __shared__ float s_alpha[128], s_beta[128];

    const int tid = threadIdx.x;
    const int wid = tid >> 5;
    const int lane = tid & 31;
    const int warp_m = wid >> 2;
    const int warp_n = wid & 3;

    if (tid < 128) {
        int c = n0 + tid;
        float s = bng[c] * rsqrtf(bnv[c] + EPS_BN);
        s_alpha[tid] = s;
        s_beta[tid]  = (bias[c] - bnm[c]) * s + bnb[c];
    }

    float acc[4][4][4];
#pragma unroll
    for (int i = 0; i < 4; i++)
#pragma unroll
        for (int j = 0; j < 4; j++)
#pragma unroll
            for (int q = 0; q < 4; q++) acc[i][j][q] = 0.0f;

    const int g = tid & 7;               // 8-col group
    const int r0 = tid >> 3;             // 0..31
    const uint32_t sb0 = smem_u32(smem);
    char* AH = smem;
    char* AL = smem + TILE_BYTES;
    char* BH = smem + 2 * TILE_BYTES;
    char* BL = smem + 3 * TILE_BYTES;
    const int kn = K >> 6;

    for (int ck = 0; ck < kn; ck++) {
        const int k0 = ck << 6;
        // ---- load + convert + store (single stage) ----
#pragma unroll
        for (int pass = 0; pass < 4; pass++) {
            const int r = r0 + 32 * pass;
            const float4* ap = (const float4*)(A + (size_t)(m0 + r) * K + k0 + g * 8);
            float4 a0 = ap[0], a1 = ap[1];
            const float4* bp = (const float4*)(Bm + (size_t)(n0 + r) * K + k0 + g * 8);
            float4 b0 = bp[0], b1 = bp[1];
            cvt8_store(AH, AL, r, g, a0, a1);
            cvt8_store(BH, BL, r, g, b0, b1);
        }
        __syncthreads();

        // ---- MMA phase ----
        {
            const int arow = warp_m * 64 + (lane & 15);
            const int ahalf = lane >> 4;
            const int bn_ = warp_n * 32 + (lane & 7);
            const int bhalf = (lane >> 3) & 1;
#pragma unroll
            for (int kb = 0; kb < 4; kb++) {
                uint32_t aH[4][4], aL[4][4], bH[4][2], bL[4][2];
#pragma unroll
                for (int mt = 0; mt < 4; mt++) {
                    const int r = arow + mt * 16;
                    const uint32_t chunk = (uint32_t)((2 * kb + ahalf) ^ (r & 7));
                    const uint32_t ad = sb0 + (uint32_t)(r * 128) + chunk * 16;
                    LDSM_X4(aH[mt][0], aH[mt][1], aH[mt][2], aH[mt][3], ad);
                    LDSM_X4(aL[mt][0], aL[mt][1], aL[mt][2], aL[mt][3], ad + TILE_BYTES);
                }
#pragma unroll
                for (int nt = 0; nt < 4; nt++) {
                    const int n = bn_ + nt * 8;
                    const uint32_t chunk = (uint32_t)((2 * kb + bhalf) ^ (n & 7));
                    const uint32_t bd = sb0 + 2u * TILE_BYTES + (uint32_t)(n * 128) + chunk * 16;
                    LDSM_X2(bH[nt][0], bH[nt][1], bd);
                    LDSM_X2(bL[nt][0], bL[nt][1], bd + TILE_BYTES);
                }
#pragma unroll
                for (int mt = 0; mt < 4; mt++)
#pragma unroll
                    for (int nt = 0; nt < 4; nt++) {
                        mma_bf16(acc[mt][nt], aH[mt], bH[nt]);
                        mma_bf16(acc[mt][nt], aH[mt], bL[nt]);
                        mma_bf16(acc[mt][nt], aL[mt], bH[nt]);
                    }
            }
        }
        __syncthreads();
    }

    // ---- epilogue ----
    const int erow = (lane >> 2);
    const int ecol = 2 * (lane & 3);
#pragma unroll
    for (int mt = 0; mt < 4; mt++) {
#pragma unroll
        for (int nt = 0; nt < 4; nt++) {
            const int lc = warp_n * 32 + nt * 8 + ecol;
            const float a0 = s_alpha[lc], a1 = s_alpha[lc + 1];
            const float b0 = s_beta[lc],  b1 = s_beta[lc + 1];
            const int gr0 = m0 + warp_m * 64 + mt * 16 + erow;
            float* p0 = C + (size_t)gr0 * Nld + n0 + lc;
            float* p1 = p0 + (size_t)8 * Nld;
            float2 v0, v1;
            v0.x = fmaxf(fmaf(acc[mt][nt][0], a0, b0), 0.0f);
            v0.y = fmaxf(fmaf(acc[mt][nt][1], a1, b1), 0.0f);
            v1.x = fmaxf(fmaf(acc[mt][nt][2], a0, b0), 0.0f);
            v1.y = fmaxf(fmaf(acc[mt][nt][3], a1, b1), 0.0f);
            if (addmode) {
                float2 o0 = *(float2*)p0;
                float2 o1 = *(float2*)p1;
                v0.x += o0.x; v0.y += o0.y;
                v1.x += o1.x; v1.y += o1.y;
            }
            *(float2*)p0 = v0;
            *(float2*)p1 = v1;
        }
    }
}

// fused 4-modality branch GEMM: z = modality
__global__ __launch_bounds__(256, 2)
void hmma_gemm4(const float* __restrict__ rgb, const float* __restrict__ depth,
                const float* __restrict__ mmwave, const float* __restrict__ lidar,
                const float* __restrict__ conv_w, const float* __restrict__ conv_b,
                const float* __restrict__ bn_g, const float* __restrict__ bn_b,
                const float* __restrict__ bn_m, const float* __restrict__ bn_v)
{
    const int z = blockIdx.z;
    const int ylim = (z < 2) ? 98 : 64;
    if (blockIdx.y >= ylim) return;
    const float* A = (z == 0) ? rgb : (z == 1) ? depth : (z == 2) ? mmwave : lidar;
    const size_t Hoff = (z == 0) ? (size_t)OFF_RGB : (z == 1) ? (size_t)OFF_DEPTH
                      : (z == 2) ? (size_t)OFF_MM : (size_t)OFF_LIDAR;
    gemm_core(A, conv_w + (size_t)z * 262144, g_H + Hoff, 512, 512,
              conv_b + z * 512, bn_g + z * 512, bn_b + z * 512,
              bn_m + z * 512, bn_v + z * 512, 0,
              blockIdx.y * 128, blockIdx.x * 128);
}

// pos-enc layer2 GEMM (accumulating into out)
__global__ __launch_bounds__(256, 2)
void hmma_gemm_pe2(const float* __restrict__ pe_w2, float* __restrict__ out,
                   const float* __restrict__ bias,
                   const float* __restrict__ bng, const float* __restrict__ bnb,
                   const float* __restrict__ bnm, const float* __restrict__ bnv)
{
    gemm_core(g_h1, pe_w2, out, 512, 128, bias, bng, bnb, bnm, bnv, 1,
              blockIdx.y * 128, blockIdx.x * 128);
}

// ---------------- threefry-2x32 ----------------
__device__ __forceinline__ unsigned rotl32(unsigned x, int d) {
    return (x << d) | (x >> (32 - d));
}
#define TF_ROUND(x0, x1, r) do { x0 += x1; x1 = rotl32(x1, r); x1 ^= x0; } while (0)
__device__ __forceinline__ void threefry2x32(unsigned k0, unsigned k1,
                                             unsigned& x0, unsigned& x1) {
    const unsigned kx = 0x1BD11BDAu ^ k0 ^ k1;
    x0 += k0; x1 += k1;
    TF_ROUND(x0, x1, 13); TF_ROUND(x0, x1, 15); TF_ROUND(x0, x1, 26); TF_ROUND(x0, x1, 6);
    x0 += k1; x1 += kx + 1u;
    TF_ROUND(x0, x1, 17); TF_ROUND(x0, x1, 29); TF_ROUND(x0, x1, 16); TF_ROUND(x0, x1, 24);
    x0 += kx; x1 += k0 + 2u;
    TF_ROUND(x0, x1, 13); TF_ROUND(x0, x1, 15); TF_ROUND(x0, x1, 26); TF_ROUND(x0, x1, 6);
    x0 += k0; x1 += k1 + 3u;
    TF_ROUND(x0, x1, 17); TF_ROUND(x0, x1, 29); TF_ROUND(x0, x1, 16); TF_ROUND(x0, x1, 24);
    x0 += k1; x1 += kx + 4u;
    TF_ROUND(x0, x1, 13); TF_ROUND(x0, x1, 15); TF_ROUND(x0, x1, 26); TF_ROUND(x0, x1, 6);
    x0 += kx; x1 += k0 + 5u;
}

__device__ __forceinline__ uint32_t redux_max_u32(uint32_t v) {
    uint32_t r;
    asm("redux.sync.max.u32 %0, %1, 0xffffffff;" : "=r"(r) : "r"(v));
    return r;
}
__device__ __forceinline__ uint32_t redux_min_u32(uint32_t v) {
    uint32_t r;
    asm("redux.sync.min.u32 %0, %1, 0xffffffff;" : "=r"(r) : "r"(v));
    return r;
}

// ---------------- FPS (512 threads, redux argmax) ----------------
__global__ __launch_bounds__(512)
void fps_kernel(const float* __restrict__ pts, float* __restrict__ nxyz) {
    extern __shared__ float sh[];
    float* xs = sh;
    float* ys = sh + 4096;
    float* zs = sh + 8192;
    __shared__ uint32_t red_v[16];
    __shared__ uint32_t red_i[16];
    __shared__ int sm_far;

    const int b = blockIdx.x;
    const int tid = threadIdx.x;
    const int lane = tid & 31;
    const int warp = tid >> 5;
    const float* p = pts + (size_t)b * 4096 * 3;
    for (int i = tid; i < 4096; i += 512) {
        xs[i] = p[3 * i + 0];
        ys[i] = p[3 * i + 1];
        zs[i] = p[3 * i + 2];
    }
    if (tid == 0) {
        unsigned a0 = 0u, a1 = 1u;
        threefry2x32(0u, 42u, a0, a1);        // derived key k2
        unsigned c0 = 0u, c1 = (unsigned)b;
        threefry2x32(a0, a1, c0, c1);
        sm_far = (int)((c0 ^ c1) & 4095u);
    }
    __syncthreads();

    float dist[8];
#pragma unroll
    for (int j = 0; j < 8; j++) dist[j] = 1e10f;

    float* outp = nxyz + (size_t)b * 128 * 3;
    for (int it = 0; it < 128; ++it) {
        const int far = sm_far;
        const float cx = xs[far], cy = ys[far], cz = zs[far];
        if (tid == 0) {
            outp[3 * it + 0] = cx;
            outp[3 * it + 1] = cy;
            outp[3 * it + 2] = cz;
        }
        float bv = -1.0f;
        int bi = 0;
        // no-FMA distance (match XLA: sub, square x3, (s0+s1)+s2); first-max kept by strict >
#pragma unroll
        for (int j = 0; j < 8; j++) {
            const int pi = (j << 9) + tid;
            float dx = __fadd_rn(xs[pi], -cx);
            float dy = __fadd_rn(ys[pi], -cy);
            float dz = __fadd_rn(zs[pi], -cz);
            float s0 = __fmul_rn(dx, dx);
            float s1 = __fmul_rn(dy, dy);
            float s2 = __fmul_rn(dz, dz);
            float d  = __fadd_rn(__fadd_rn(s0, s1), s2);
            float nd = fminf(dist[j], d);
            dist[j] = nd;
            if (nd > bv) { bv = nd; bi = pi; }   // ascending pi -> strict > keeps lowest
        }
        // warp argmax via redux (dist >= 0 so float bits order == u32 order)
        uint32_t bvu = __float_as_uint(bv);
        uint32_t gv = redux_max_u32(bvu);
        uint32_t cand = (bvu == gv) ? (uint32_t)bi : 0xFFFFFFFFu;
        uint32_t gi = redux_min_u32(cand);
        if (lane == 0) { red_v[warp] = gv; red_i[warp] = gi; }
        __syncthreads();
        if (tid < 32) {
            uint32_t v = (lane < 16) ? red_v[lane] : 0u;
            uint32_t i = (lane < 16) ? red_i[lane] : 0xFFFFFFFFu;
            uint32_t gv2 = redux_max_u32(v);
            uint32_t cand2 = (v == gv2) ? i : 0xFFFFFFFFu;
            uint32_t gi2 = redux_min_u32(cand2);
            if (lane == 0) sm_far = (int)gi2;
        }
        __syncthreads();
    }
}

// ---------------- token-mix linear (L -> 32) + ReLU ----------------
__global__ void mix_kernel(
    const float* __restrict__ lin_w_img, const float* __restrict__ lin_b_img,
    const float* __restrict__ lin_w_pc,  const float* __restrict__ lin_b_pc,
    float* __restrict__ out)
{
    __shared__ float lw[32 * 49];
    __shared__ float lb[32];
    __shared__ float smH[49 * 32];

    const int o0 = blockIdx.x * 32;
    const int b = blockIdx.y;
    const int mod = blockIdx.z;
    const int tid = threadIdx.x;
    const int Lm = (mod < 2) ? 49 : 32;

    const float* wsrc = (mod == 0) ? lin_w_img
                      : (mod == 1) ? lin_w_img + 32 * 49
                      : (mod == 2) ? lin_w_pc
                                   : lin_w_pc + 32 * 32;
    const float* bsrc = (mod == 0) ? lin_b_img
                      : (mod == 1) ? lin_b_img + 32
                      : (mod == 2) ? lin_b_pc
                                   : lin_b_pc + 32;
    size_t Hoff = (mod == 0) ? (size_t)OFF_RGB
                : (mod == 1) ? (size_t)OFF_DEPTH
                : (mod == 2) ? (size_t)OFF_MM
                             : (size_t)OFF_LIDAR;
    const float* Hb = g_H + Hoff + (size_t)b * Lm * 512;

    for (int i = tid; i < 32 * Lm; i += 256) lw[i] = wsrc[i];
    if (tid < 32) lb[tid] = bsrc[tid];
    for (int i = tid; i < Lm * 32; i += 256) {
        int l = i >> 5, o = i & 31;
        smH[i] = Hb[(size_t)l * 512 + o0 + o];
    }
    __syncthreads();

#pragma unroll
    for (int p = 0; p < 4; p++) {
        int lin = tid + (p << 8);
        int k = lin >> 5, o = lin & 31;
        float acc = lb[k];
        for (int l = 0; l < Lm; l++) acc += smH[l * 32 + o] * lw[k * Lm + l];
        acc = fmaxf(acc, 0.0f);
        out[((size_t)b * 128 + mod * 32 + k) * 512 + o0 + o] = acc;
    }
}

// ---------------- pos-enc layer1: 3 -> 128, BN, ReLU ----------------
__global__ void pe1_kernel(
    const float* __restrict__ w1, const float* __restrict__ b1,
    const float* __restrict__ g1, const float* __restrict__ bb1,
    const float* __restrict__ m1, const float* __restrict__ v1)
{
    int idx = blockIdx.x * 256 + threadIdx.x;
    int row = idx >> 7, c = idx & 127;
    const float* xyz = g_newxyz + (size_t)row * 3;
    float x = xyz[0], y = xyz[1], z = xyz[2];
    float acc = w1[c * 3 + 0] * x + w1[c * 3 + 1] * y + w1[c * 3 + 2] * z + b1[c];
    float s = g1[c] / sqrtf(v1[c] + EPS_BN);
    g_h1[idx] = fmaxf((acc - m1[c]) * s + bb1[c], 0.0f);
}

// ---------------- launch ----------------
extern "C" void kernel_launch(void* const* d_in, const int* in_sizes, int n_in,
                              void* d_out, int out_size) {
    (void)in_sizes; (void)n_in; (void)out_size;
    const float* rgb       = (const float*)d_in[0];
    const float* depth     = (const float*)d_in[1];
    const float* mmwave    = (const float*)d_in[2];
    const float* lidar     = (const float*)d_in[3];
    const float* pts       = (const float*)d_in[4];
    const float* conv_w    = (const float*)d_in[5];
    const float* conv_b    = (const float*)d_in[6];
    const float* bn_g      = (const float*)d_in[7];
    const float* bn_b      = (const float*)d_in[8];
    const float* bn_m      = (const float*)d_in[9];
    const float* bn_v      = (const float*)d_in[10];
    const float* lin_w_img = (const float*)d_in[11];
    const float* lin_b_img = (const float*)d_in[12];
    const float* lin_w_pc  = (const float*)d_in[13];
    const float* lin_b_pc  = (const float*)d_in[14];
    const float* pe_w1     = (const float*)d_in[15];
    const float* pe_b1     = (const float*)d_in[16];
    const float* pe_g1     = (const float*)d_in[17];
    const float* pe_bb1    = (const float*)d_in[18];
    const float* pe_m1     = (const float*)d_in[19];
    const float* pe_v1     = (const float*)d_in[20];
    const float* pe_w2     = (const float*)d_in[21];
    const float* pe_b2     = (const float*)d_in[22];
    const float* pe_g2     = (const float*)d_in[23];
    const float* pe_bb2    = (const float*)d_in[24];
    const float* pe_m2     = (const float*)d_in[25];
    const float* pe_v2     = (const float*)d_in[26];
    float* out = (float*)d_out;

    float *nx;
    cudaGetSymbolAddress((void**)&nx, g_newxyz);

    cudaFuncSetAttribute(fps_kernel, cudaFuncAttributeMaxDynamicSharedMemorySize, 50176);
    cudaFuncSetAttribute(hmma_gemm4, cudaFuncAttributeMaxDynamicSharedMemorySize, GEMM_SMEM);
    cudaFuncSetAttribute(hmma_gemm_pe2, cudaFuncAttributeMaxDynamicSharedMemorySize, GEMM_SMEM);

    // FPS -> new_xyz
    fps_kernel<<<256, 512, 49152>>>(pts, nx);

    // fused 4-modality branch GEMM (bf16-split HMMA)
    hmma_gemm4<<<dim3(4, 98, 4), 256, GEMM_SMEM>>>(rgb, depth, mmwave, lidar,
        conv_w, conv_b, bn_g, bn_b, bn_m, bn_v);

    // token mix -> writes all of out (proj)
    mix_kernel<<<dim3(16, 256, 4), 256>>>(lin_w_img, lin_b_img, lin_w_pc, lin_b_pc, out);

    // pos-enc layer1 (needs FPS result)
    pe1_kernel<<<16384, 256>>>(pe_w1, pe_b1, pe_g1, pe_bb1, pe_m1, pe_v1);

    // pos-enc layer2 GEMM, bn+relu, accumulated into out
    hmma_gemm_pe2<<<dim3(4, 256), 256, GEMM_SMEM>>>(pe_w2, out,
        pe_b2, pe_g2, pe_bb2, pe_m2, pe_v2);
}

// round 9
// speedup vs baseline: 2.2708x; 1.0937x over previous
#include <cuda_runtime.h>
#include <cuda_bf16.h>
#include <math.h>
#include <stdint.h>

#define EPS_BN 1e-5f

// ---------------- scratch ----------------
#define OFF_RGB   0
#define OFF_DEPTH 6422528      // 256*49*512
#define OFF_MM    12845056
#define OFF_LIDAR 17039360
__device__ float g_H[21233664];
__device__ float g_newxyz[256 * 128 * 3];

// pre-split weights (hi/lo bf16), row-major as source
#define W_PE2_OFF (4 * 512 * 512)
#define W_TOTAL   (4 * 512 * 512 + 512 * 128)
__device__ __nv_bfloat16 g_wh[W_TOTAL];
__device__ __nv_bfloat16 g_wl[W_TOTAL];
// folded pos-enc layer1 coeffs: W0,W1,W2,B per channel (out = relu(x*W0+y*W1+z*W2+B))
__device__ float g_peA[128 * 4];

// ---------------- helpers ----------------
__device__ __forceinline__ uint32_t smem_u32(const void* p) {
    uint32_t a;
    asm("{ .reg .u64 t; cvta.to.shared.u64 t, %1; cvt.u32.u64 %0, t; }" : "=r"(a) : "l"(p));
    return a;
}
__device__ __forceinline__ void cp16(uint32_t dst, const void* src) {
    asm volatile("cp.async.cg.shared.global [%0], [%1], 16;" :: "r"(dst), "l"(src));
}
#define CP_COMMIT() asm volatile("cp.async.commit_group;" ::: "memory")
#define CP_WAIT0()  asm volatile("cp.async.wait_group 0;" ::: "memory")

__device__ __forceinline__ void mma_bf16(float* c, const uint32_t* a, const uint32_t* b) {
    asm volatile(
        "mma.sync.aligned.m16n8k16.row.col.f32.bf16.bf16.f32 "
        "{%0,%1,%2,%3}, {%4,%5,%6,%7}, {%8,%9}, {%0,%1,%2,%3};"
        : "+f"(c[0]), "+f"(c[1]), "+f"(c[2]), "+f"(c[3])
        : "r"(a[0]), "r"(a[1]), "r"(a[2]), "r"(a[3]), "r"(b[0]), "r"(b[1]));
}
#define LDSM_X4(r0, r1, r2, r3, addr)                                        \
    asm volatile("ldmatrix.sync.aligned.m8n8.x4.shared.b16 {%0,%1,%2,%3}, [%4];" \
                 : "=r"(r0), "=r"(r1), "=r"(r2), "=r"(r3) : "r"(addr))
#define LDSM_X2(r0, r1, addr)                                                \
    asm volatile("ldmatrix.sync.aligned.m8n8.x2.shared.b16 {%0,%1}, [%2];"   \
                 : "=r"(r0), "=r"(r1) : "r"(addr))

// tile geometry: 128 rows x 64 bf16 cols = 128 B/row = 16384 B per tile
#define TILE_BYTES 16384
// smem: AH[0,16K) AL[16K,32K) | B stage0 [32K,64K) | B stage1 [64K,96K)
#define GEMM_SMEM 98304

__device__ __forceinline__ uint32_t pack_bf16x2(float x, float y) {
    uint32_t h;
    asm("cvt.rn.bf16x2.f32 %0, %1, %2;" : "=r"(h) : "f"(y), "f"(x));
    return h;
}
__device__ __forceinline__ void split2(float x, float y, uint32_t& hi, uint32_t& lo) {
    hi = pack_bf16x2(x, y);
    __nv_bfloat162 h2 = *(__nv_bfloat162*)&hi;
    lo = pack_bf16x2(x - __bfloat162float(h2.x), y - __bfloat162float(h2.y));
}
// 8 consecutive fp32 cols -> hi/lo bf16 16B chunks, swizzled store
__device__ __forceinline__ void cvt8_store(char* baseH, char* baseL, int r, int g,
                                           float4 v0, float4 v1) {
    uint4 hi, lo;
    split2(v0.x, v0.y, hi.x, lo.x);
    split2(v0.z, v0.w, hi.y, lo.y);
    split2(v1.x, v1.y, hi.z, lo.z);
    split2(v1.z, v1.w, hi.w, lo.w);
    uint32_t off = (uint32_t)(r * 128 + ((g ^ (r & 7)) << 4));
    *(uint4*)(baseH + off) = hi;
    *(uint4*)(baseL + off) = lo;
}

// ---------------- bf16-split HMMA GEMM core ----------------
// GEN=0: A loaded from fp32 global. GEN=1: A generated from g_newxyz via g_peA (pe1 fused).
// B from pre-split g_wh/g_wl via cp.async (double-buffered).
template<int GEN>
__device__ __forceinline__ void gemm_core_w(
    const float* __restrict__ A,
    const __nv_bfloat16* __restrict__ Wh, const __nv_bfloat16* __restrict__ Wl,
    float* __restrict__ C, int Nld, int K,
    const float* __restrict__ bias,
    const float* __restrict__ bng, const float* __restrict__ bnb,
    const float* __restrict__ bnm, const float* __restrict__ bnv,
    int addmode, int m0, int n0)
{
    extern __shared__ char smem[];
    __shared__ float s_alpha[128], s_beta[128];

    const int tid = threadIdx.x;
    const int wid = tid >> 5;
    const int lane = tid & 31;
    const int warp_m = wid >> 2;
    const int warp_n = wid & 3;

    if (tid < 128) {
        int c = n0 + tid;
        float s = bng[c] * rsqrtf(bnv[c] + EPS_BN);
        s_alpha[tid] = s;
        s_beta[tid]  = (bias[c] - bnm[c]) * s + bnb[c];
    }

    float acc[4][4][4];
#pragma unroll
    for (int i = 0; i < 4; i++)
#pragma unroll
        for (int j = 0; j < 4; j++)
#pragma unroll
            for (int q = 0; q < 4; q++) acc[i][j][q] = 0.0f;

    const int g = tid & 7;               // 8-col group
    const int r0 = tid >> 3;             // 0..31
    const uint32_t sb0 = smem_u32(smem);
    const uint32_t sbB = sb0 + 2u * TILE_BYTES;
    char* AH = smem;
    char* AL = smem + TILE_BYTES;
    const int kn = K >> 6;

#define ISSUE_B(ck) do {                                                      \
        const int bk0 = (ck) << 6;                                            \
        const uint32_t bb = sbB + (uint32_t)(((ck) & 1) << 15);               \
        _Pragma("unroll")                                                     \
        for (int pass = 0; pass < 4; pass++) {                                \
            const int r = r0 + 32 * pass;                                     \
            const size_t woff = (size_t)(n0 + r) * K + bk0 + g * 8;           \
            const uint32_t off = (uint32_t)(r * 128 + ((g ^ (r & 7)) << 4));  \
            cp16(bb + off, Wh + woff);                                        \
            cp16(bb + TILE_BYTES + off, Wl + woff);                           \
        }                                                                     \
        CP_COMMIT();                                                          \
    } while (0)

    ISSUE_B(0);

    for (int ck = 0; ck < kn; ck++) {
        const int k0 = ck << 6;
        // ---- A convert/generate (single stage; protected by trailing syncthreads) ----
#pragma unroll
        for (int pass = 0; pass < 4; pass++) {
            const int r = r0 + 32 * pass;
            float4 a0, a1;
            if (GEN) {
                const float* xyz = g_newxyz + (size_t)(m0 + r) * 3;
                const float px = xyz[0], py = xyz[1], pz = xyz[2];
                float v[8];
#pragma unroll
                for (int q = 0; q < 8; q++) {
                    const float* co = g_peA + 4 * (k0 + g * 8 + q);
                    v[q] = fmaxf(fmaf(px, co[0], fmaf(py, co[1], fmaf(pz, co[2], co[3]))), 0.0f);
                }
                a0 = make_float4(v[0], v[1], v[2], v[3]);
                a1 = make_float4(v[4], v[5], v[6], v[7]);
            } else {
                const float4* ap = (const float4*)(A + (size_t)(m0 + r) * K + k0 + g * 8);
                a0 = ap[0];
                a1 = ap[1];
            }
            cvt8_store(AH, AL, r, g, a0, a1);
        }
        CP_WAIT0();              // B(ck) is the only outstanding group here
        __syncthreads();
        if (ck + 1 < kn) ISSUE_B(ck + 1);   // overlaps MMA(ck) + A(ck+1)

        // ---- MMA phase ----
        {
            const uint32_t bbase = sbB + (uint32_t)((ck & 1) << 15);
            const int arow = warp_m * 64 + (lane & 15);
            const int ahalf = lane >> 4;
            const int bn_ = warp_n * 32 + (lane & 7);
            const int bhalf = (lane >> 3) & 1;
#pragma unroll
            for (int kb = 0; kb < 4; kb++) {
                uint32_t aH[4][4], aL[4][4], bH[4][2], bL[4][2];
#pragma unroll
                for (int mt = 0; mt < 4; mt++) {
                    const int r = arow + mt * 16;
                    const uint32_t chunk = (uint32_t)((2 * kb + ahalf) ^ (r & 7));
                    const uint32_t ad = sb0 + (uint32_t)(r * 128) + chunk * 16;
                    LDSM_X4(aH[mt][0], aH[mt][1], aH[mt][2], aH[mt][3], ad);
                    LDSM_X4(aL[mt][0], aL[mt][1], aL[mt][2], aL[mt][3], ad + TILE_BYTES);
                }
#pragma unroll
                for (int nt = 0; nt < 4; nt++) {
                    const int n = bn_ + nt * 8;
                    const uint32_t chunk = (uint32_t)((2 * kb + bhalf) ^ (n & 7));
                    const uint32_t bd = bbase + (uint32_t)(n * 128) + chunk * 16;
                    LDSM_X2(bH[nt][0], bH[nt][1], bd);
                    LDSM_X2(bL[nt][0], bL[nt][1], bd + TILE_BYTES);
                }
#pragma unroll
                for (int mt = 0; mt < 4; mt++)
#pragma unroll
                    for (int nt = 0; nt < 4; nt++) {
                        mma_bf16(acc[mt][nt], aH[mt], bH[nt]);
                        mma_bf16(acc[mt][nt], aH[mt], bL[nt]);
                        mma_bf16(acc[mt][nt], aL[mt], bH[nt]);
                    }
            }
        }
        __syncthreads();
    }
#undef ISSUE_B

    // ---- epilogue ----
    const int erow = (lane >> 2);
    const int ecol = 2 * (lane & 3);
#pragma unroll
    for (int mt = 0; mt < 4; mt++) {
#pragma unroll
        for (int nt = 0; nt < 4; nt++) {
            const int lc = warp_n * 32 + nt * 8 + ecol;
            const float a0 = s_alpha[lc], a1 = s_alpha[lc + 1];
            const float b0 = s_beta[lc],  b1 = s_beta[lc + 1];
            const int gr0 = m0 + warp_m * 64 + mt * 16 + erow;
            float* p0 = C + (size_t)gr0 * Nld + n0 + lc;
            float* p1 = p0 + (size_t)8 * Nld;
            float2 v0, v1;
            v0.x = fmaxf(fmaf(acc[mt][nt][0], a0, b0), 0.0f);
            v0.y = fmaxf(fmaf(acc[mt][nt][1], a1, b1), 0.0f);
            v1.x = fmaxf(fmaf(acc[mt][nt][2], a0, b0), 0.0f);
            v1.y = fmaxf(fmaf(acc[mt][nt][3], a1, b1), 0.0f);
            if (addmode) {
                float2 o0 = *(float2*)p0;
                float2 o1 = *(float2*)p1;
                v0.x += o0.x; v0.y += o0.y;
                v1.x += o1.x; v1.y += o1.y;
            }
            *(float2*)p0 = v0;
            *(float2*)p1 = v1;
        }
    }
}

// fused 4-modality branch GEMM (flattened grid: y in [0,324))
__global__ __launch_bounds__(256, 2)
void hmma_gemm4(const float* __restrict__ rgb, const float* __restrict__ depth,
                const float* __restrict__ mmwave, const float* __restrict__ lidar,
                const float* __restrict__ conv_b,
                const float* __restrict__ bn_g, const float* __restrict__ bn_b,
                const float* __restrict__ bn_m, const float* __restrict__ bn_v)
{
    const int y = blockIdx.y;
    int z, yl;
    if (y < 98)       { z = 0; yl = y; }
    else if (y < 196) { z = 1; yl = y - 98; }
    else if (y < 260) { z = 2; yl = y - 196; }
    else              { z = 3; yl = y - 260; }
    const float* A = (z == 0) ? rgb : (z == 1) ? depth : (z == 2) ? mmwave : lidar;
    const size_t Hoff = (z == 0) ? (size_t)OFF_RGB : (z == 1) ? (size_t)OFF_DEPTH
                      : (z == 2) ? (size_t)OFF_MM : (size_t)OFF_LIDAR;
    gemm_core_w<0>(A, g_wh + (size_t)z * 262144, g_wl + (size_t)z * 262144,
                   g_H + Hoff, 512, 512,
                   conv_b + z * 512, bn_g + z * 512, bn_b + z * 512,
                   bn_m + z * 512, bn_v + z * 512, 0,
                   yl * 128, blockIdx.x * 128);
}

// pos-enc layer2 GEMM with fused layer1 A-generation, accumulating into out
__global__ __launch_bounds__(256, 2)
void hmma_pe2(float* __restrict__ out,
              const float* __restrict__ bias,
              const float* __restrict__ bng, const float* __restrict__ bnb,
              const float* __restrict__ bnm, const float* __restrict__ bnv)
{
    gemm_core_w<1>(nullptr, g_wh + W_PE2_OFF, g_wl + W_PE2_OFF,
                   out, 512, 128, bias, bng, bnb, bnm, bnv, 1,
                   blockIdx.y * 128, blockIdx.x * 128);
}

// ---------------- prep: split weights to bf16 hi/lo + fold pe1 coeffs ----------------
__global__ void prep_kernel(const float* __restrict__ conv_w, const float* __restrict__ pe_w2,
                            const float* __restrict__ pe_w1, const float* __restrict__ pe_b1,
                            const float* __restrict__ pe_g1, const float* __restrict__ pe_bb1,
                            const float* __restrict__ pe_m1, const float* __restrict__ pe_v1)
{
    int idx = blockIdx.x * 256 + threadIdx.x;
    if (idx < W_TOTAL) {
        float v = (idx < W_PE2_OFF) ? conv_w[idx] : pe_w2[idx - W_PE2_OFF];
        __nv_bfloat16 h = __float2bfloat16(v);
        g_wh[idx] = h;
        g_wl[idx] = __float2bfloat16(v - __bfloat162float(h));
    }
    if (blockIdx.x == 0 && threadIdx.x < 128) {
        int c = threadIdx.x;
        float s = pe_g1[c] * rsqrtf(pe_v1[c] + EPS_BN);
        g_peA[c * 4 + 0] = pe_w1[c * 3 + 0] * s;
        g_peA[c * 4 + 1] = pe_w1[c * 3 + 1] * s;
        g_peA[c * 4 + 2] = pe_w1[c * 3 + 2] * s;
        g_peA[c * 4 + 3] = (pe_b1[c] - pe_m1[c]) * s + pe_bb1[c];
    }
}

// ---------------- threefry-2x32 ----------------
__device__ __forceinline__ unsigned rotl32(unsigned x, int d) {
    return (x << d) | (x >> (32 - d));
}
#define TF_ROUND(x0, x1, r) do { x0 += x1; x1 = rotl32(x1, r); x1 ^= x0; } while (0)
__device__ __forceinline__ void threefry2x32(unsigned k0, unsigned k1,
                                             unsigned& x0, unsigned& x1) {
    const unsigned kx = 0x1BD11BDAu ^ k0 ^ k1;
    x0 += k0; x1 += k1;
    TF_ROUND(x0, x1, 13); TF_ROUND(x0, x1, 15); TF_ROUND(x0, x1, 26); TF_ROUND(x0, x1, 6);
    x0 += k1; x1 += kx + 1u;
    TF_ROUND(x0, x1, 17); TF_ROUND(x0, x1, 29); TF_ROUND(x0, x1, 16); TF_ROUND(x0, x1, 24);
    x0 += kx; x1 += k0 + 2u;
    TF_ROUND(x0, x1, 13); TF_ROUND(x0, x1, 15); TF_ROUND(x0, x1, 26); TF_ROUND(x0, x1, 6);
    x0 += k0; x1 += k1 + 3u;
    TF_ROUND(x0, x1, 17); TF_ROUND(x0, x1, 29); TF_ROUND(x0, x1, 16); TF_ROUND(x0, x1, 24);
    x0 += k1; x1 += kx + 4u;
    TF_ROUND(x0, x1, 13); TF_ROUND(x0, x1, 15); TF_ROUND(x0, x1, 26); TF_ROUND(x0, x1, 6);
    x0 += kx; x1 += k0 + 5u;
}

__device__ __forceinline__ uint32_t redux_max_u32(uint32_t v) {
    uint32_t r;
    asm("redux.sync.max.u32 %0, %1, 0xffffffff;" : "=r"(r) : "r"(v));
    return r;
}
__device__ __forceinline__ uint32_t redux_min_u32(uint32_t v) {
    uint32_t r;
    asm("redux.sync.min.u32 %0, %1, 0xffffffff;" : "=r"(r) : "r"(v));
    return r;
}

// ---------------- FPS (512 threads, redux argmax) ----------------
__global__ __launch_bounds__(512)
void fps_kernel(const float* __restrict__ pts, float* __restrict__ nxyz) {
    extern __shared__ float sh[];
    float* xs = sh;
    float* ys = sh + 4096;
    float* zs = sh + 8192;
    __shared__ uint32_t red_v[16];
    __shared__ uint32_t red_i[16];
    __shared__ int sm_far;

    const int b = blockIdx.x;
    const int tid = threadIdx.x;
    const int lane = tid & 31;
    const int warp = tid >> 5;
    const float* p = pts + (size_t)b * 4096 * 3;
    for (int i = tid; i < 4096; i += 512) {
        xs[i] = p[3 * i + 0];
        ys[i] = p[3 * i + 1];
        zs[i] = p[3 * i + 2];
    }
    if (tid == 0) {
        unsigned a0 = 0u, a1 = 1u;
        threefry2x32(0u, 42u, a0, a1);        // derived key k2
        unsigned c0 = 0u, c1 = (unsigned)b;
        threefry2x32(a0, a1, c0, c1);
        sm_far = (int)((c0 ^ c1) & 4095u);
    }
    __syncthreads();

    float dist[8];
#pragma unroll
    for (int j = 0; j < 8; j++) dist[j] = 1e10f;

    float* outp = nxyz + (size_t)b * 128 * 3;
    for (int it = 0; it < 128; ++it) {
        const int far = sm_far;
        const float cx = xs[far], cy = ys[far], cz = zs[far];
        if (tid == 0) {
            outp[3 * it + 0] = cx;
            outp[3 * it + 1] = cy;
            outp[3 * it + 2] = cz;
        }
        float bv = -1.0f;
        int bi = 0;
        // no-FMA distance (match XLA: sub, square x3, (s0+s1)+s2); ascending pi + strict > keeps first max
#pragma unroll
        for (int j = 0; j < 8; j++) {
            const int pi = (j << 9) + tid;
            float dx = __fadd_rn(xs[pi], -cx);
            float dy = __fadd_rn(ys[pi], -cy);
            float dz = __fadd_rn(zs[pi], -cz);
            float s0 = __fmul_rn(dx, dx);
            float s1 = __fmul_rn(dy, dy);
            float s2 = __fmul_rn(dz, dz);
            float d  = __fadd_rn(__fadd_rn(s0, s1), s2);
            float nd = fminf(dist[j], d);
            dist[j] = nd;
            if (nd > bv) { bv = nd; bi = pi; }
        }
        uint32_t bvu = __float_as_uint(bv);
        uint32_t gv = redux_max_u32(bvu);
        uint32_t cand = (bvu == gv) ? (uint32_t)bi : 0xFFFFFFFFu;
        uint32_t gi = redux_min_u32(cand);
        if (lane == 0) { red_v[warp] = gv; red_i[warp] = gi; }
        __syncthreads();
        if (tid < 32) {
            uint32_t v = (lane < 16) ? red_v[lane] : 0u;
            uint32_t i = (lane < 16) ? red_i[lane] : 0xFFFFFFFFu;
            uint32_t gv2 = redux_max_u32(v);
            uint32_t cand2 = (v == gv2) ? i : 0xFFFFFFFFu;
            uint32_t gi2 = redux_min_u32(cand2);
            if (lane == 0) sm_far = (int)gi2;
        }
        __syncthreads();
    }
}

// ---------------- token-mix linear (L -> 32) + ReLU ----------------
__global__ void mix_kernel(
    const float* __restrict__ lin_w_img, const float* __restrict__ lin_b_img,
    const float* __restrict__ lin_w_pc,  const float* __restrict__ lin_b_pc,
    float* __restrict__ out)
{
    __shared__ float lw[32 * 49];
    __shared__ float lb[32];
    __shared__ float smH[49 * 32];

    const int o0 = blockIdx.x * 32;
    const int b = blockIdx.y;
    const int mod = blockIdx.z;
    const int tid = threadIdx.x;
    const int Lm = (mod < 2) ? 49 : 32;

    const float* wsrc = (mod == 0) ? lin_w_img
                      : (mod == 1) ? lin_w_img + 32 * 49
                      : (mod == 2) ? lin_w_pc
                                   : lin_w_pc + 32 * 32;
    const float* bsrc = (mod == 0) ? lin_b_img
                      : (mod == 1) ? lin_b_img + 32
                      : (mod == 2) ? lin_b_pc
                                   : lin_b_pc + 32;
    size_t Hoff = (mod == 0) ? (size_t)OFF_RGB
                : (mod == 1) ? (size_t)OFF_DEPTH
                : (mod == 2) ? (size_t)OFF_MM
                             : (size_t)OFF_LIDAR;
    const float* Hb = g_H + Hoff + (size_t)b * Lm * 512;

    for (int i = tid; i < 32 * Lm; i += 256) lw[i] = wsrc[i];
    if (tid < 32) lb[tid] = bsrc[tid];
    for (int i = tid; i < Lm * 32; i += 256) {
        int l = i >> 5, o = i & 31;
        smH[i] = Hb[(size_t)l * 512 + o0 + o];
    }
    __syncthreads();

#pragma unroll
    for (int p = 0; p < 4; p++) {
        int lin = tid + (p << 8);
        int k = lin >> 5, o = lin & 31;
        float acc = lb[k];
        for (int l = 0; l < Lm; l++) acc += smH[l * 32 + o] * lw[k * Lm + l];
        acc = fmaxf(acc, 0.0f);
        out[((size_t)b * 128 + mod * 32 + k) * 512 + o0 + o] = acc;
    }
}

// ---------------- launch ----------------
extern "C" void kernel_launch(void* const* d_in, const int* in_sizes, int n_in,
                              void* d_out, int out_size) {
    (void)in_sizes; (void)n_in; (void)out_size;
    const float* rgb       = (const float*)d_in[0];
    const float* depth     = (const float*)d_in[1];
    const float* mmwave    = (const float*)d_in[2];
    const float* lidar     = (const float*)d_in[3];
    const float* pts       = (const float*)d_in[4];
    const float* conv_w    = (const float*)d_in[5];
    const float* conv_b    = (const float*)d_in[6];
    const float* bn_g      = (const float*)d_in[7];
    const float* bn_b      = (const float*)d_in[8];
    const float* bn_m      = (const float*)d_in[9];
    const float* bn_v      = (const float*)d_in[10];
    const float* lin_w_img = (const float*)d_in[11];
    const float* lin_b_img = (const float*)d_in[12];
    const float* lin_w_pc  = (const float*)d_in[13];
    const float* lin_b_pc  = (const float*)d_in[14];
    const float* pe_w1     = (const float*)d_in[15];
    const float* pe_b1     = (const float*)d_in[16];
    const float* pe_g1     = (const float*)d_in[17];
    const float* pe_bb1    = (const float*)d_in[18];
    const float* pe_m1     = (const float*)d_in[19];
    const float* pe_v1     = (const float*)d_in[20];
    const float* pe_w2     = (const float*)d_in[21];
    const float* pe_b2     = (const float*)d_in[22];
    const float* pe_g2     = (const float*)d_in[23];
    const float* pe_bb2    = (const float*)d_in[24];
    const float* pe_m2     = (const float*)d_in[25];
    const float* pe_v2     = (const float*)d_in[26];
    float* out = (float*)d_out;

    float* nx;
    cudaGetSymbolAddress((void**)&nx, g_newxyz);

    static cudaStream_t s2 = nullptr;
    static cudaEvent_t evA = nullptr, evB = nullptr;
    if (!s2) {
        cudaStreamCreateWithFlags(&s2, cudaStreamNonBlocking);
        cudaEventCreateWithFlags(&evA, cudaEventDisableTiming);
        cudaEventCreateWithFlags(&evB, cudaEventDisableTiming);
        cudaFuncSetAttribute(fps_kernel, cudaFuncAttributeMaxDynamicSharedMemorySize, 50176);
        cudaFuncSetAttribute(hmma_gemm4, cudaFuncAttributeMaxDynamicSharedMemorySize, GEMM_SMEM);
        cudaFuncSetAttribute(hmma_pe2, cudaFuncAttributeMaxDynamicSharedMemorySize, GEMM_SMEM);
    }

    // fork: FPS runs on side stream concurrently with prep/GEMM4/mix
    cudaEventRecord(evA, 0);
    cudaStreamWaitEvent(s2, evA, 0);
    fps_kernel<<<256, 512, 49152, s2>>>(pts, nx);
    cudaEventRecord(evB, s2);

    // main stream: weight prep -> branch GEMMs -> token mix
    prep_kernel<<<(W_TOTAL + 255) / 256, 256>>>(conv_w, pe_w2, pe_w1, pe_b1,
                                                pe_g1, pe_bb1, pe_m1, pe_v1);
    hmma_gemm4<<<dim3(4, 324), 256, GEMM_SMEM>>>(rgb, depth, mmwave, lidar,
        conv_b, bn_g, bn_b, bn_m, bn_v);
    mix_kernel<<<dim3(16, 256, 4), 256>>>(lin_w_img, lin_b_img, lin_w_pc, lin_b_pc, out);

    // join: pe2 (fused pe1) needs FPS output
    cudaStreamWaitEvent(0, evB, 0);
    hmma_pe2<<<dim3(4, 256), 256, GEMM_SMEM>>>(out, pe_b2, pe_g2, pe_bb2, pe_m2, pe_v2);
}

// round 12
// speedup vs baseline: 2.3474x; 1.0337x over previous
#include <cuda_runtime.h>
#include <cuda_bf16.h>
#include <math.h>
#include <stdint.h>

#define EPS_BN 1e-5f

// ---------------- scratch ----------------
#define OFF_RGB   0
#define OFF_DEPTH 6422528      // 256*49*512
#define OFF_MM    12845056
#define OFF_LIDAR 17039360
__device__ float g_H[21233664];
__device__ float g_newxyz[256 * 128 * 3];

// pre-split weights (hi/lo bf16), row-major as source
#define W_PE2_OFF (4 * 512 * 512)
#define W_TOTAL   (4 * 512 * 512 + 512 * 128)
__device__ __nv_bfloat16 g_wh[W_TOTAL];
__device__ __nv_bfloat16 g_wl[W_TOTAL];
// folded pos-enc layer1 coeffs: W0,W1,W2,B per channel
__device__ float g_peA[128 * 4];
// block-diagonal mix weight, padded to [128, 192], bf16 hi/lo + row bias
__device__ __nv_bfloat16 g_mwh[128 * 192];
__device__ __nv_bfloat16 g_mwl[128 * 192];
__device__ float g_mlb[128];

// ---------------- helpers ----------------
__device__ __forceinline__ uint32_t smem_u32(const void* p) {
    uint32_t a;
    asm("{ .reg .u64 t; cvta.to.shared.u64 t, %1; cvt.u32.u64 %0, t; }" : "=r"(a) : "l"(p));
    return a;
}
__device__ __forceinline__ void cp16(uint32_t dst, const void* src) {
    asm volatile("cp.async.cg.shared.global [%0], [%1], 16;" :: "r"(dst), "l"(src));
}
#define CP_COMMIT() asm volatile("cp.async.commit_group;" ::: "memory")
#define CP_WAIT0()  asm volatile("cp.async.wait_group 0;" ::: "memory")

__device__ __forceinline__ void mma_bf16(float* c, const uint32_t* a, const uint32_t* b) {
    asm volatile(
        "mma.sync.aligned.m16n8k16.row.col.f32.bf16.bf16.f32 "
        "{%0,%1,%2,%3}, {%4,%5,%6,%7}, {%8,%9}, {%0,%1,%2,%3};"
        : "+f"(c[0]), "+f"(c[1]), "+f"(c[2]), "+f"(c[3])
        : "r"(a[0]), "r"(a[1]), "r"(a[2]), "r"(a[3]), "r"(b[0]), "r"(b[1]));
}
#define LDSM_X4(r0, r1, r2, r3, addr)                                        \
    asm volatile("ldmatrix.sync.aligned.m8n8.x4.shared.b16 {%0,%1,%2,%3}, [%4];" \
                 : "=r"(r0), "=r"(r1), "=r"(r2), "=r"(r3) : "r"(addr))
#define LDSM_X2(r0, r1, addr)                                                \
    asm volatile("ldmatrix.sync.aligned.m8n8.x2.shared.b16 {%0,%1}, [%2];"   \
                 : "=r"(r0), "=r"(r1) : "r"(addr))

#define TILE_BYTES 16384
#define GEMM_SMEM 98304

__device__ __forceinline__ uint32_t pack_bf16x2(float x, float y) {
    uint32_t h;
    asm("cvt.rn.bf16x2.f32 %0, %1, %2;" : "=r"(h) : "f"(y), "f"(x));
    return h;
}
__device__ __forceinline__ void split2(float x, float y, uint32_t& hi, uint32_t& lo) {
    hi = pack_bf16x2(x, y);
    __nv_bfloat162 h2 = *(__nv_bfloat162*)&hi;
    lo = pack_bf16x2(x - __bfloat162float(h2.x), y - __bfloat162float(h2.y));
}
__device__ __forceinline__ void cvt8_store(char* baseH, char* baseL, int r, int g,
                                           float4 v0, float4 v1) {
    uint4 hi, lo;
    split2(v0.x, v0.y, hi.x, lo.x);
    split2(v0.z, v0.w, hi.y, lo.y);
    split2(v1.x, v1.y, hi.z, lo.z);
    split2(v1.z, v1.w, hi.w, lo.w);
    uint32_t off = (uint32_t)(r * 128 + ((g ^ (r & 7)) << 4));
    *(uint4*)(baseH + off) = hi;
    *(uint4*)(baseL + off) = lo;
}

// ---------------- bf16-split HMMA GEMM core (branch GEMMs + pe2) ----------------
template<int GEN>
__device__ __forceinline__ void gemm_core_w(
    const float* __restrict__ A,
    const __nv_bfloat16* __restrict__ Wh, const __nv_bfloat16* __restrict__ Wl,
    float* __restrict__ C, int Nld, int K,
    const float* __restrict__ bias,
    const float* __restrict__ bng, const float* __restrict__ bnb,
    const float* __restrict__ bnm, const float* __restrict__ bnv,
    int addmode, int m0, int n0)
{
    extern __shared__ char smem[];
    __shared__ float s_alpha[128], s_beta[128];

    const int tid = threadIdx.x;
    const int wid = tid >> 5;
    const int lane = tid & 31;
    const int warp_m = wid >> 2;
    const int warp_n = wid & 3;

    if (tid < 128) {
        int c = n0 + tid;
        float s = bng[c] * rsqrtf(bnv[c] + EPS_BN);
        s_alpha[tid] = s;
        s_beta[tid]  = (bias[c] - bnm[c]) * s + bnb[c];
    }

    float acc[4][4][4];
#pragma unroll
    for (int i = 0; i < 4; i++)
#pragma unroll
        for (int j = 0; j < 4; j++)
#pragma unroll
            for (int q = 0; q < 4; q++) acc[i][j][q] = 0.0f;

    const int g = tid & 7;
    const int r0 = tid >> 3;
    const uint32_t sb0 = smem_u32(smem);
    const uint32_t sbB = sb0 + 2u * TILE_BYTES;
    char* AH = smem;
    char* AL = smem + TILE_BYTES;
    const int kn = K >> 6;

#define ISSUE_B(ck) do {                                                      \
        const int bk0 = (ck) << 6;                                            \
        const uint32_t bb = sbB + (uint32_t)(((ck) & 1) << 15);               \
        _Pragma("unroll")                                                     \
        for (int pass = 0; pass < 4; pass++) {                                \
            const int r = r0 + 32 * pass;                                     \
            const size_t woff = (size_t)(n0 + r) * K + bk0 + g * 8;           \
            const uint32_t off = (uint32_t)(r * 128 + ((g ^ (r & 7)) << 4));  \
            cp16(bb + off, Wh + woff);                                        \
            cp16(bb + TILE_BYTES + off, Wl + woff);                           \
        }                                                                     \
        CP_COMMIT();                                                          \
    } while (0)

    ISSUE_B(0);

    for (int ck = 0; ck < kn; ck++) {
        const int k0 = ck << 6;
#pragma unroll
        for (int pass = 0; pass < 4; pass++) {
            const int r = r0 + 32 * pass;
            float4 a0, a1;
            if (GEN) {
                const float* xyz = g_newxyz + (size_t)(m0 + r) * 3;
                const float px = xyz[0], py = xyz[1], pz = xyz[2];
                float v[8];
#pragma unroll
                for (int q = 0; q < 8; q++) {
                    const float* co = g_peA + 4 * (k0 + g * 8 + q);
                    v[q] = fmaxf(fmaf(px, co[0], fmaf(py, co[1], fmaf(pz, co[2], co[3]))), 0.0f);
                }
                a0 = make_float4(v[0], v[1], v[2], v[3]);
                a1 = make_float4(v[4], v[5], v[6], v[7]);
            } else {
                const float4* ap = (const float4*)(A + (size_t)(m0 + r) * K + k0 + g * 8);
                a0 = ap[0];
                a1 = ap[1];
            }
            cvt8_store(AH, AL, r, g, a0, a1);
        }
        CP_WAIT0();
        __syncthreads();
        if (ck + 1 < kn) ISSUE_B(ck + 1);

        {
            const uint32_t bbase = sbB + (uint32_t)((ck & 1) << 15);
            const int arow = warp_m * 64 + (lane & 15);
            const int ahalf = lane >> 4;
            const int bn_ = warp_n * 32 + (lane & 7);
            const int bhalf = (lane >> 3) & 1;
#pragma unroll
            for (int kb = 0; kb < 4; kb++) {
                uint32_t aH[4][4], aL[4][4], bH[4][2], bL[4][2];
#pragma unroll
                for (int mt = 0; mt < 4; mt++) {
                    const int r = arow + mt * 16;
                    const uint32_t chunk = (uint32_t)((2 * kb + ahalf) ^ (r & 7));
                    const uint32_t ad = sb0 + (uint32_t)(r * 128) + chunk * 16;
                    LDSM_X4(aH[mt][0], aH[mt][1], aH[mt][2], aH[mt][3], ad);
                    LDSM_X4(aL[mt][0], aL[mt][1], aL[mt][2], aL[mt][3], ad + TILE_BYTES);
                }
#pragma unroll
                for (int nt = 0; nt < 4; nt++) {
                    const int n = bn_ + nt * 8;
                    const uint32_t chunk = (uint32_t)((2 * kb + bhalf) ^ (n & 7));
                    const uint32_t bd = bbase + (uint32_t)(n * 128) + chunk * 16;
                    LDSM_X2(bH[nt][0], bH[nt][1], bd);
                    LDSM_X2(bL[nt][0], bL[nt][1], bd + TILE_BYTES);
                }
#pragma unroll
                for (int mt = 0; mt < 4; mt++)
#pragma unroll
                    for (int nt = 0; nt < 4; nt++) {
                        mma_bf16(acc[mt][nt], aH[mt], bH[nt]);
                        mma_bf16(acc[mt][nt], aH[mt], bL[nt]);
                        mma_bf16(acc[mt][nt], aL[mt], bH[nt]);
                    }
            }
        }
        __syncthreads();
    }
#undef ISSUE_B

    const int erow = (lane >> 2);
    const int ecol = 2 * (lane & 3);
#pragma unroll
    for (int mt = 0; mt < 4; mt++) {
#pragma unroll
        for (int nt = 0; nt < 4; nt++) {
            const int lc = warp_n * 32 + nt * 8 + ecol;
            const float a0 = s_alpha[lc], a1 = s_alpha[lc + 1];
            const float b0 = s_beta[lc],  b1 = s_beta[lc + 1];
            const int gr0 = m0 + warp_m * 64 + mt * 16 + erow;
            float* p0 = C + (size_t)gr0 * Nld + n0 + lc;
            float* p1 = p0 + (size_t)8 * Nld;
            float2 v0, v1;
            v0.x = fmaxf(fmaf(acc[mt][nt][0], a0, b0), 0.0f);
            v0.y = fmaxf(fmaf(acc[mt][nt][1], a1, b1), 0.0f);
            v1.x = fmaxf(fmaf(acc[mt][nt][2], a0, b0), 0.0f);
            v1.y = fmaxf(fmaf(acc[mt][nt][3], a1, b1), 0.0f);
            if (addmode) {
                float2 o0 = *(float2*)p0;
                float2 o1 = *(float2*)p1;
                v0.x += o0.x; v0.y += o0.y;
                v1.x += o1.x; v1.y += o1.y;
            }
            *(float2*)p0 = v0;
            *(float2*)p1 = v1;
        }
    }
}

__global__ __launch_bounds__(256, 2)
void hmma_gemm4(const float* __restrict__ rgb, const float* __restrict__ depth,
                const float* __restrict__ mmwave, const float* __restrict__ lidar,
                const float* __restrict__ conv_b,
                const float* __restrict__ bn_g, const float* __restrict__ bn_b,
                const float* __restrict__ bn_m, const float* __restrict__ bn_v)
{
    const int y = blockIdx.y;
    int z, yl;
    if (y < 98)       { z = 0; yl = y; }
    else if (y < 196) { z = 1; yl = y - 98; }
    else if (y < 260) { z = 2; yl = y - 196; }
    else              { z = 3; yl = y - 260; }
    const float* A = (z == 0) ? rgb : (z == 1) ? depth : (z == 2) ? mmwave : lidar;
    const size_t Hoff = (z == 0) ? (size_t)OFF_RGB : (z == 1) ? (size_t)OFF_DEPTH
                      : (z == 2) ? (size_t)OFF_MM : (size_t)OFF_LIDAR;
    gemm_core_w<0>(A, g_wh + (size_t)z * 262144, g_wl + (size_t)z * 262144,
                   g_H + Hoff, 512, 512,
                   conv_b + z * 512, bn_g + z * 512, bn_b + z * 512,
                   bn_m + z * 512, bn_v + z * 512, 0,
                   yl * 128, blockIdx.x * 128);
}

__global__ __launch_bounds__(256, 2)
void hmma_pe2(float* __restrict__ out,
              const float* __restrict__ bias,
              const float* __restrict__ bng, const float* __restrict__ bnb,
              const float* __restrict__ bnm, const float* __restrict__ bnv)
{
    gemm_core_w<1>(nullptr, g_wh + W_PE2_OFF, g_wl + W_PE2_OFF,
                   out, 512, 128, bias, bng, bnb, bnm, bnv, 1,
                   blockIdx.y * 128, blockIdx.x * 128);
}

// ---------------- mix as HMMA: Out[b] = relu(Wblk[128,192] @ Hcat[192, 512] + lb) ----------------
__device__ __forceinline__ const float* h_row(int lcat, int b, int n0) {
    if (lcat < 49)  return g_H + OFF_RGB   + ((size_t)b * 49 + lcat) * 512 + n0;
    if (lcat < 98)  return g_H + OFF_DEPTH + ((size_t)b * 49 + (lcat - 49)) * 512 + n0;
    if (lcat < 130) return g_H + OFF_MM    + ((size_t)b * 32 + (lcat - 98)) * 512 + n0;
    if (lcat < 162) return g_H + OFF_LIDAR + ((size_t)b * 32 + (lcat - 130)) * 512 + n0;
    return nullptr;
}

__global__ __launch_bounds__(256, 2)
void mix_hmma(float* __restrict__ out)
{
    extern __shared__ char smem[];       // A stage0 [0,32K) | A stage1 [32K,64K) | B [64K,96K)
    __shared__ float s_rb[128];

    const int tid = threadIdx.x;
    const int wid = tid >> 5;
    const int lane = tid & 31;
    const int warp_m = wid >> 2;
    const int warp_n = wid & 3;
    const int n0 = blockIdx.x * 128;     // o tile
    const int b  = blockIdx.y;

    if (tid < 128) s_rb[tid] = g_mlb[tid];

    float acc[4][4][4];
#pragma unroll
    for (int i = 0; i < 4; i++)
#pragma unroll
        for (int j = 0; j < 4; j++)
#pragma unroll
            for (int q = 0; q < 4; q++) acc[i][j][q] = 0.0f;

    const int g = tid & 7;
    const int r0 = tid >> 3;
    const uint32_t sb0 = smem_u32(smem);
    const uint32_t sbB = sb0 + 65536u;
    char* BH = smem + 65536;
    char* BL = BH + TILE_BYTES;
    const int on = tid & 127;            // local o row for transpose
    const int lgrp = tid >> 7;           // 0/1 -> which 32-l half

#define ISSUE_A(ck) do {                                                      \
        const int ak0 = (ck) << 6;                                            \
        const uint32_t ab = sb0 + (uint32_t)(((ck) & 1) << 15);               \
        _Pragma("unroll")                                                     \
        for (int pass = 0; pass < 4; pass++) {                                \
            const int r = r0 + 32 * pass;                                     \
            const size_t woff = (size_t)r * 192 + ak0 + g * 8;                \
            const uint32_t off = (uint32_t)(r * 128 + ((g ^ (r & 7)) << 4));  \
            cp16(ab + off, g_mwh + woff);                                     \
            cp16(ab + TILE_BYTES + off, g_mwl + woff);                        \
        }                                                                     \
        CP_COMMIT();                                                          \
    } while (0)

    ISSUE_A(0);

    for (int ck = 0; ck < 3; ck++) {
        // ---- transpose H chunk into B tiles (single stage) ----
#pragma unroll
        for (int lp = 0; lp < 16; lp++) {
            const int c = lgrp * 32 + 2 * lp;          // local k col (even)
            const int lcat = (ck << 6) + c;
            const float* p0 = h_row(lcat, b, n0);
            const float* p1 = h_row(lcat + 1, b, n0);
            float v0 = p0 ? p0[on] : 0.0f;
            float v1 = p1 ? p1[on] : 0.0f;
            uint32_t hi, lo;
            split2(v0, v1, hi, lo);
            const uint32_t off = (uint32_t)(on * 128 + ((((c >> 3) ^ (on & 7)) << 4)) + ((c & 7) << 1));
            *(uint32_t*)(BH + off) = hi;
            *(uint32_t*)(BL + off) = lo;
        }
        CP_WAIT0();
        __syncthreads();
        if (ck + 1 < 3) ISSUE_A(ck + 1);

        // ---- MMA ----
        {
            const uint32_t abase = sb0 + (uint32_t)((ck & 1) << 15);
            const int arow = warp_m * 64 + (lane & 15);
            const int ahalf = lane >> 4;
            const int bn_ = warp_n * 32 + (lane & 7);
            const int bhalf = (lane >> 3) & 1;
#pragma unroll
            for (int kb = 0; kb < 4; kb++) {
                uint32_t aH[4][4], aL[4][4], bH[4][2], bL[4][2];
#pragma unroll
                for (int mt = 0; mt < 4; mt++) {
                    const int r = arow + mt * 16;
                    const uint32_t chunk = (uint32_t)((2 * kb + ahalf) ^ (r & 7));
                    const uint32_t ad = abase + (uint32_t)(r * 128) + chunk * 16;
                    LDSM_X4(aH[mt][0], aH[mt][1], aH[mt][2], aH[mt][3], ad);
                    LDSM_X4(aL[mt][0], aL[mt][1], aL[mt][2], aL[mt][3], ad + TILE_BYTES);
                }
#pragma unroll
                for (int nt = 0; nt < 4; nt++) {
                    const int n = bn_ + nt * 8;
                    const uint32_t chunk = (uint32_t)((2 * kb + bhalf) ^ (n & 7));
                    const uint32_t bd = sbB + (uint32_t)(n * 128) + chunk * 16;
                    LDSM_X2(bH[nt][0], bH[nt][1], bd);
                    LDSM_X2(bL[nt][0], bL[nt][1], bd + TILE_BYTES);
                }
#pragma unroll
                for (int mt = 0; mt < 4; mt++)
#pragma unroll
                    for (int nt = 0; nt < 4; nt++) {
                        mma_bf16(acc[mt][nt], aH[mt], bH[nt]);
                        mma_bf16(acc[mt][nt], aH[mt], bL[nt]);
                        mma_bf16(acc[mt][nt], aL[mt], bH[nt]);
                    }
            }
        }
        __syncthreads();
    }
#undef ISSUE_A

    // ---- epilogue: relu(acc + rowbias), C[m=krow, n=o] -> out[(b*128+m)*512 + n0+n] ----
    const int erow = (lane >> 2);
    const int ecol = 2 * (lane & 3);
#pragma unroll
    for (int mt = 0; mt < 4; mt++) {
        const int row = warp_m * 64 + mt * 16 + erow;
        const float rb0 = s_rb[row];
        const float rb1 = s_rb[row + 8];
#pragma unroll
        for (int nt = 0; nt < 4; nt++) {
            const int lc = warp_n * 32 + nt * 8 + ecol;
            float* p0 = out + ((size_t)b * 128 + row) * 512 + n0 + lc;
            float* p1 = p0 + (size_t)8 * 512;
            float2 v0, v1;
            v0.x = fmaxf(acc[mt][nt][0] + rb0, 0.0f);
            v0.y = fmaxf(acc[mt][nt][1] + rb0, 0.0f);
            v1.x = fmaxf(acc[mt][nt][2] + rb1, 0.0f);
            v1.y = fmaxf(acc[mt][nt][3] + rb1, 0.0f);
            *(float2*)p0 = v0;
            *(float2*)p1 = v1;
        }
    }
}

// ---------------- prep: split weights + fold pe1 + build mix Wblk ----------------
__global__ void prep_kernel(const float* __restrict__ conv_w, const float* __restrict__ pe_w2,
                            const float* __restrict__ pe_w1, const float* __restrict__ pe_b1,
                            const float* __restrict__ pe_g1, const float* __restrict__ pe_bb1,
                            const float* __restrict__ pe_m1, const float* __restrict__ pe_v1,
                            const float* __restrict__ lin_w_img, const float* __restrict__ lin_b_img,
                            const float* __restrict__ lin_w_pc,  const float* __restrict__ lin_b_pc)
{
    int idx = blockIdx.x * 256 + threadIdx.x;
    if (idx < W_TOTAL) {
        float v = (idx < W_PE2_OFF) ? conv_w[idx] : pe_w2[idx - W_PE2_OFF];
        __nv_bfloat16 h = __float2bfloat16(v);
        g_wh[idx] = h;
        g_wl[idx] = __float2bfloat16(v - __bfloat162float(h));
    }
    if (idx < 128 * 192) {
        const int krow = idx / 192, lcat = idx % 192;
        const int mod = krow >> 5, k = krow & 31;
        float w = 0.0f;
        if (mod == 0)      { if (lcat < 49)                w = lin_w_img[k * 49 + lcat]; }
        else if (mod == 1) { if (lcat >= 49 && lcat < 98)  w = lin_w_img[(32 + k) * 49 + lcat - 49]; }
        else if (mod == 2) { if (lcat >= 98 && lcat < 130) w = lin_w_pc[k * 32 + lcat - 98]; }
        else               { if (lcat >= 130 && lcat < 162) w = lin_w_pc[(32 + k) * 32 + lcat - 130]; }
        __nv_bfloat16 h = __float2bfloat16(w);
        g_mwh[idx] = h;
        g_mwl[idx] = __float2bfloat16(w - __bfloat162float(h));
    }
    if (idx < 128) {
        const int mod = idx >> 5, k = idx & 31;
        g_mlb[idx] = (mod == 0) ? lin_b_img[k] : (mod == 1) ? lin_b_img[32 + k]
                   : (mod == 2) ? lin_b_pc[k] : lin_b_pc[32 + k];
        float s = pe_g1[idx] * rsqrtf(pe_v1[idx] + EPS_BN);
        g_peA[idx * 4 + 0] = pe_w1[idx * 3 + 0] * s;
        g_peA[idx * 4 + 1] = pe_w1[idx * 3 + 1] * s;
        g_peA[idx * 4 + 2] = pe_w1[idx * 3 + 2] * s;
        g_peA[idx * 4 + 3] = (pe_b1[idx] - pe_m1[idx]) * s + pe_bb1[idx];
    }
}

// ---------------- threefry-2x32 ----------------
__device__ __forceinline__ unsigned rotl32(unsigned x, int d) {
    return (x << d) | (x >> (32 - d));
}
#define TF_ROUND(x0, x1, r) do { x0 += x1; x1 = rotl32(x1, r); x1 ^= x0; } while (0)
__device__ __forceinline__ void threefry2x32(unsigned k0, unsigned k1,
                                             unsigned& x0, unsigned& x1) {
    const unsigned kx = 0x1BD11BDAu ^ k0 ^ k1;
    x0 += k0; x1 += k1;
    TF_ROUND(x0, x1, 13); TF_ROUND(x0, x1, 15); TF_ROUND(x0, x1, 26); TF_ROUND(x0, x1, 6);
    x0 += k1; x1 += kx + 1u;
    TF_ROUND(x0, x1, 17); TF_ROUND(x0, x1, 29); TF_ROUND(x0, x1, 16); TF_ROUND(x0, x1, 24);
    x0 += kx; x1 += k0 + 2u;
    TF_ROUND(x0, x1, 13); TF_ROUND(x0, x1, 15); TF_ROUND(x0, x1, 26); TF_ROUND(x0, x1, 6);
    x0 += k0; x1 += k1 + 3u;
    TF_ROUND(x0, x1, 17); TF_ROUND(x0, x1, 29); TF_ROUND(x0, x1, 16); TF_ROUND(x0, x1, 24);
    x0 += k1; x1 += kx + 4u;
    TF_ROUND(x0, x1, 13); TF_ROUND(x0, x1, 15); TF_ROUND(x0, x1, 26); TF_ROUND(x0, x1, 6);
    x0 += kx; x1 += k0 + 5u;
}
__device__ __forceinline__ uint32_t redux_max_u32(uint32_t v) {
    uint32_t r;
    asm("redux.sync.max.u32 %0, %1, 0xffffffff;" : "=r"(r) : "r"(v));
    return r;
}
__device__ __forceinline__ uint32_t redux_min_u32(uint32_t v) {
    uint32_t r;
    asm("redux.sync.min.u32 %0, %1, 0xffffffff;" : "=r"(r) : "r"(v));
    return r;
}

// ---------------- FPS ----------------
__global__ __launch_bounds__(512)
void fps_kernel(const float* __restrict__ pts, float* __restrict__ nxyz) {
    extern __shared__ float sh[];
    float* xs = sh;
    float* ys = sh + 4096;
    float* zs = sh + 8192;
    __shared__ uint32_t red_v[16];
    __shared__ uint32_t red_i[16];
    __shared__ int sm_far;

    const int b = blockIdx.x;
    const int tid = threadIdx.x;
    const int lane = tid & 31;
    const int warp = tid >> 5;
    const float* p = pts + (size_t)b * 4096 * 3;
    for (int i = tid; i < 4096; i += 512) {
        xs[i] = p[3 * i + 0];
        ys[i] = p[3 * i + 1];
        zs[i] = p[3 * i + 2];
    }
    if (tid == 0) {
        unsigned a0 = 0u, a1 = 1u;
        threefry2x32(0u, 42u, a0, a1);
        unsigned c0 = 0u, c1 = (unsigned)b;
        threefry2x32(a0, a1, c0, c1);
        sm_far = (int)((c0 ^ c1) & 4095u);
    }
    __syncthreads();

    float dist[8];
#pragma unroll
    for (int j = 0; j < 8; j++) dist[j] = 1e10f;

    float* outp = nxyz + (size_t)b * 128 * 3;
    for (int it = 0; it < 128; ++it) {
        const int far = sm_far;
        const float cx = xs[far], cy = ys[far], cz = zs[far];
        if (tid == 0) {
            outp[3 * it + 0] = cx;
            outp[3 * it + 1] = cy;
            outp[3 * it + 2] = cz;
        }
        float bv = -1.0f;
        int bi = 0;
#pragma unroll
        for (int j = 0; j < 8; j++) {
            const int pi = (j << 9) + tid;
            float dx = __fadd_rn(xs[pi], -cx);
            float dy = __fadd_rn(ys[pi], -cy);
            float dz = __fadd_rn(zs[pi], -cz);
            float s0 = __fmul_rn(dx, dx);
            float s1 = __fmul_rn(dy, dy);
            float s2 = __fmul_rn(dz, dz);
            float d  = __fadd_rn(__fadd_rn(s0, s1), s2);
            float nd = fminf(dist[j], d);
            dist[j] = nd;
            if (nd > bv) { bv = nd; bi = pi; }
        }
        uint32_t bvu = __float_as_uint(bv);
        uint32_t gv = redux_max_u32(bvu);
        uint32_t cand = (bvu == gv) ? (uint32_t)bi : 0xFFFFFFFFu;
        uint32_t gi = redux_min_u32(cand);
        if (lane == 0) { red_v[warp] = gv; red_i[warp] = gi; }
        __syncthreads();
        if (tid < 32) {
            uint32_t v = (lane < 16) ? red_v[lane] : 0u;
            uint32_t i = (lane < 16) ? red_i[lane] : 0xFFFFFFFFu;
            uint32_t gv2 = redux_max_u32(v);
            uint32_t cand2 = (v == gv2) ? i : 0xFFFFFFFFu;
            uint32_t gi2 = redux_min_u32(cand2);
            if (lane == 0) sm_far = (int)gi2;
        }
        __syncthreads();
    }
}

// ---------------- launch ----------------
extern "C" void kernel_launch(void* const* d_in, const int* in_sizes, int n_in,
                              void* d_out, int out_size) {
    (void)in_sizes; (void)n_in; (void)out_size;
    const float* rgb       = (const float*)d_in[0];
    const float* depth     = (const float*)d_in[1];
    const float* mmwave    = (const float*)d_in[2];
    const float* lidar     = (const float*)d_in[3];
    const float* pts       = (const float*)d_in[4];
    const float* conv_w    = (const float*)d_in[5];
    const float* conv_b    = (const float*)d_in[6];
    const float* bn_g      = (const float*)d_in[7];
    const float* bn_b      = (const float*)d_in[8];
    const float* bn_m      = (const float*)d_in[9];
    const float* bn_v      = (const float*)d_in[10];
    const float* lin_w_img = (const float*)d_in[11];
    const float* lin_b_img = (const float*)d_in[12];
    const float* lin_w_pc  = (const float*)d_in[13];
    const float* lin_b_pc  = (const float*)d_in[14];
    const float* pe_w1     = (const float*)d_in[15];
    const float* pe_b1     = (const float*)d_in[16];
    const float* pe_g1     = (const float*)d_in[17];
    const float* pe_bb1    = (const float*)d_in[18];
    const float* pe_m1     = (const float*)d_in[19];
    const float* pe_v1     = (const float*)d_in[20];
    const float* pe_w2     = (const float*)d_in[21];
    const float* pe_b2     = (const float*)d_in[22];
    const float* pe_g2     = (const float*)d_in[23];
    const float* pe_bb2    = (const float*)d_in[24];
    const float* pe_m2     = (const float*)d_in[25];
    const float* pe_v2     = (const float*)d_in[26];
    float* out = (float*)d_out;

    float* nx;
    cudaGetSymbolAddress((void**)&nx, g_newxyz);

    static cudaStream_t s2 = nullptr;
    static cudaEvent_t evA = nullptr, evB = nullptr;
    if (!s2) {
        cudaStreamCreateWithFlags(&s2, cudaStreamNonBlocking);
        cudaEventCreateWithFlags(&evA, cudaEventDisableTiming);
        cudaEventCreateWithFlags(&evB, cudaEventDisableTiming);
        cudaFuncSetAttribute(fps_kernel, cudaFuncAttributeMaxDynamicSharedMemorySize, 50176);
        cudaFuncSetAttribute(hmma_gemm4, cudaFuncAttributeMaxDynamicSharedMemorySize, GEMM_SMEM);
        cudaFuncSetAttribute(hmma_pe2, cudaFuncAttributeMaxDynamicSharedMemorySize, GEMM_SMEM);
        cudaFuncSetAttribute(mix_hmma, cudaFuncAttributeMaxDynamicSharedMemorySize, GEMM_SMEM);
    }

    // fork: FPS runs on side stream concurrently with prep/GEMM4/mix
    cudaEventRecord(evA, 0);
    cudaStreamWaitEvent(s2, evA, 0);
    fps_kernel<<<256, 512, 49152, s2>>>(pts, nx);
    cudaEventRecord(evB, s2);

    // main stream
    prep_kernel<<<(W_TOTAL + 255) / 256, 256>>>(conv_w, pe_w2, pe_w1, pe_b1,
                                                pe_g1, pe_bb1, pe_m1, pe_v1,
                                                lin_w_img, lin_b_img, lin_w_pc, lin_b_pc);
    hmma_gemm4<<<dim3(4, 324), 256, GEMM_SMEM>>>(rgb, depth, mmwave, lidar,
        conv_b, bn_g, bn_b, bn_m, bn_v);
    mix_hmma<<<dim3(4, 256), 256, GEMM_SMEM>>>(out);

    // join: pe2 (fused pe1) needs FPS output
    cudaStreamWaitEvent(0, evB, 0);
    hmma_pe2<<<dim3(4, 256), 256, GEMM_SMEM>>>(out, pe_b2, pe_g2, pe_bb2, pe_m2, pe_v2);
}

// round 13
// speedup vs baseline: 2.3679x; 1.0087x over previous
#include <cuda_runtime.h>
#include <cuda_bf16.h>
#include <math.h>
#include <stdint.h>

#define EPS_BN 1e-5f

// ---------------- scratch ----------------
#define OFF_RGB   0
#define OFF_DEPTH 6422528      // 256*49*512
#define OFF_MM    12845056
#define OFF_LIDAR 17039360
__device__ float g_H[21233664];
__device__ float g_newxyz[256 * 128 * 3];
__device__ float g_pe[16777216];                 // pe2 relu-term [B*128, 512]

// pre-split weights (hi/lo bf16), row-major as source
#define W_PE2_OFF (4 * 512 * 512)
#define W_TOTAL   (4 * 512 * 512 + 512 * 128)
__device__ __nv_bfloat16 g_wh[W_TOTAL];
__device__ __nv_bfloat16 g_wl[W_TOTAL];
// folded pos-enc layer1 coeffs
__device__ float g_peA[128 * 4];
// block-diagonal mix weight, padded to [128, 192], bf16 hi/lo + row bias
__device__ __nv_bfloat16 g_mwh[128 * 192];
__device__ __nv_bfloat16 g_mwl[128 * 192];
__device__ float g_mlb[128];
// transposed H: [b, o, lcat-pad192] bf16 hi/lo
__device__ __nv_bfloat16 g_hth[256 * 512 * 192];
__device__ __nv_bfloat16 g_htl[256 * 512 * 192];

// ---------------- helpers ----------------
__device__ __forceinline__ uint32_t smem_u32(const void* p) {
    uint32_t a;
    asm("{ .reg .u64 t; cvta.to.shared.u64 t, %1; cvt.u32.u64 %0, t; }" : "=r"(a) : "l"(p));
    return a;
}
__device__ __forceinline__ void cp16(uint32_t dst, const void* src) {
    asm volatile("cp.async.cg.shared.global [%0], [%1], 16;" :: "r"(dst), "l"(src));
}
#define CP_COMMIT() asm volatile("cp.async.commit_group;" ::: "memory")
#define CP_WAIT0()  asm volatile("cp.async.wait_group 0;" ::: "memory")
#define CP_WAIT1()  asm volatile("cp.async.wait_group 1;" ::: "memory")

__device__ __forceinline__ void mma_bf16(float* c, const uint32_t* a, const uint32_t* b) {
    asm volatile(
        "mma.sync.aligned.m16n8k16.row.col.f32.bf16.bf16.f32 "
        "{%0,%1,%2,%3}, {%4,%5,%6,%7}, {%8,%9}, {%0,%1,%2,%3};"
        : "+f"(c[0]), "+f"(c[1]), "+f"(c[2]), "+f"(c[3])
        : "r"(a[0]), "r"(a[1]), "r"(a[2]), "r"(a[3]), "r"(b[0]), "r"(b[1]));
}
#define LDSM_X4(r0, r1, r2, r3, addr)                                        \
    asm volatile("ldmatrix.sync.aligned.m8n8.x4.shared.b16 {%0,%1,%2,%3}, [%4];" \
                 : "=r"(r0), "=r"(r1), "=r"(r2), "=r"(r3) : "r"(addr))
#define LDSM_X2(r0, r1, addr)                                                \
    asm volatile("ldmatrix.sync.aligned.m8n8.x2.shared.b16 {%0,%1}, [%2];"   \
                 : "=r"(r0), "=r"(r1) : "r"(addr))

#define TILE_BYTES 16384
#define GEMM_SMEM 98304
#define MIX_SMEM  131072

__device__ __forceinline__ uint32_t pack_bf16x2(float x, float y) {
    uint32_t h;
    asm("cvt.rn.bf16x2.f32 %0, %1, %2;" : "=r"(h) : "f"(y), "f"(x));
    return h;
}
__device__ __forceinline__ void split2(float x, float y, uint32_t& hi, uint32_t& lo) {
    hi = pack_bf16x2(x, y);
    __nv_bfloat162 h2 = *(__nv_bfloat162*)&hi;
    lo = pack_bf16x2(x - __bfloat162float(h2.x), y - __bfloat162float(h2.y));
}
__device__ __forceinline__ void cvt8_store(char* baseH, char* baseL, int r, int g,
                                           float4 v0, float4 v1) {
    uint4 hi, lo;
    split2(v0.x, v0.y, hi.x, lo.x);
    split2(v0.z, v0.w, hi.y, lo.y);
    split2(v1.x, v1.y, hi.z, lo.z);
    split2(v1.z, v1.w, hi.w, lo.w);
    uint32_t off = (uint32_t)(r * 128 + ((g ^ (r & 7)) << 4));
    *(uint4*)(baseH + off) = hi;
    *(uint4*)(baseL + off) = lo;
}

// ---------------- bf16-split HMMA GEMM core (branch GEMMs + pe2) ----------------
template<int GEN>
__device__ __forceinline__ void gemm_core_w(
    const float* __restrict__ A,
    const __nv_bfloat16* __restrict__ Wh, const __nv_bfloat16* __restrict__ Wl,
    float* __restrict__ C, int Nld, int K,
    const float* __restrict__ bias,
    const float* __restrict__ bng, const float* __restrict__ bnb,
    const float* __restrict__ bnm, const float* __restrict__ bnv,
    int addmode, int m0, int n0)
{
    extern __shared__ char smem[];
    __shared__ float s_alpha[128], s_beta[128];

    const int tid = threadIdx.x;
    const int wid = tid >> 5;
    const int lane = tid & 31;
    const int warp_m = wid >> 2;
    const int warp_n = wid & 3;

    if (tid < 128) {
        int c = n0 + tid;
        float s = bng[c] * rsqrtf(bnv[c] + EPS_BN);
        s_alpha[tid] = s;
        s_beta[tid]  = (bias[c] - bnm[c]) * s + bnb[c];
    }

    float acc[4][4][4];
#pragma unroll
    for (int i = 0; i < 4; i++)
#pragma unroll
        for (int j = 0; j < 4; j++)
#pragma unroll
            for (int q = 0; q < 4; q++) acc[i][j][q] = 0.0f;

    const int g = tid & 7;
    const int r0 = tid >> 3;
    const uint32_t sb0 = smem_u32(smem);
    const uint32_t sbB = sb0 + 2u * TILE_BYTES;
    char* AH = smem;
    char* AL = smem + TILE_BYTES;
    const int kn = K >> 6;

#define ISSUE_B(ck) do {                                                      \
        const int bk0 = (ck) << 6;                                            \
        const uint32_t bb = sbB + (uint32_t)(((ck) & 1) << 15);               \
        _Pragma("unroll")                                                     \
        for (int pass = 0; pass < 4; pass++) {                                \
            const int r = r0 + 32 * pass;                                     \
            const size_t woff = (size_t)(n0 + r) * K + bk0 + g * 8;           \
            const uint32_t off = (uint32_t)(r * 128 + ((g ^ (r & 7)) << 4));  \
            cp16(bb + off, Wh + woff);                                        \
            cp16(bb + TILE_BYTES + off, Wl + woff);                           \
        }                                                                     \
        CP_COMMIT();                                                          \
    } while (0)

    ISSUE_B(0);

    for (int ck = 0; ck < kn; ck++) {
        const int k0 = ck << 6;
#pragma unroll
        for (int pass = 0; pass < 4; pass++) {
            const int r = r0 + 32 * pass;
            float4 a0, a1;
            if (GEN) {
                const float* xyz = g_newxyz + (size_t)(m0 + r) * 3;
                const float px = xyz[0], py = xyz[1], pz = xyz[2];
                float v[8];
#pragma unroll
                for (int q = 0; q < 8; q++) {
                    const float* co = g_peA + 4 * (k0 + g * 8 + q);
                    v[q] = fmaxf(fmaf(px, co[0], fmaf(py, co[1], fmaf(pz, co[2], co[3]))), 0.0f);
                }
                a0 = make_float4(v[0], v[1], v[2], v[3]);
                a1 = make_float4(v[4], v[5], v[6], v[7]);
            } else {
                const float4* ap = (const float4*)(A + (size_t)(m0 + r) * K + k0 + g * 8);
                a0 = ap[0];
                a1 = ap[1];
            }
            cvt8_store(AH, AL, r, g, a0, a1);
        }
        CP_WAIT0();
        __syncthreads();
        if (ck + 1 < kn) ISSUE_B(ck + 1);

        {
            const uint32_t bbase = sbB + (uint32_t)((ck & 1) << 15);
            const int arow = warp_m * 64 + (lane & 15);
            const int ahalf = lane >> 4;
            const int bn_ = warp_n * 32 + (lane & 7);
            const int bhalf = (lane >> 3) & 1;
#pragma unroll
            for (int kb = 0; kb < 4; kb++) {
                uint32_t aH[4][4], aL[4][4], bH[4][2], bL[4][2];
#pragma unroll
                for (int mt = 0; mt < 4; mt++) {
                    const int r = arow + mt * 16;
                    const uint32_t chunk = (uint32_t)((2 * kb + ahalf) ^ (r & 7));
                    const uint32_t ad = sb0 + (uint32_t)(r * 128) + chunk * 16;
                    LDSM_X4(aH[mt][0], aH[mt][1], aH[mt][2], aH[mt][3], ad);
                    LDSM_X4(aL[mt][0], aL[mt][1], aL[mt][2], aL[mt][3], ad + TILE_BYTES);
                }
#pragma unroll
                for (int nt = 0; nt < 4; nt++) {
                    const int n = bn_ + nt * 8;
                    const uint32_t chunk = (uint32_t)((2 * kb + bhalf) ^ (n & 7));
                    const uint32_t bd = bbase + (uint32_t)(n * 128) + chunk * 16;
                    LDSM_X2(bH[nt][0], bH[nt][1], bd);
                    LDSM_X2(bL[nt][0], bL[nt][1], bd + TILE_BYTES);
                }
#pragma unroll
                for (int mt = 0; mt < 4; mt++)
#pragma unroll
                    for (int nt = 0; nt < 4; nt++) {
                        mma_bf16(acc[mt][nt], aH[mt], bH[nt]);
                        mma_bf16(acc[mt][nt], aH[mt], bL[nt]);
                        mma_bf16(acc[mt][nt], aL[mt], bH[nt]);
                    }
            }
        }
        __syncthreads();
    }
#undef ISSUE_B

    const int erow = (lane >> 2);
    const int ecol = 2 * (lane & 3);
#pragma unroll
    for (int mt = 0; mt < 4; mt++) {
#pragma unroll
        for (int nt = 0; nt < 4; nt++) {
            const int lc = warp_n * 32 + nt * 8 + ecol;
            const float a0 = s_alpha[lc], a1 = s_alpha[lc + 1];
            const float b0 = s_beta[lc],  b1 = s_beta[lc + 1];
            const int gr0 = m0 + warp_m * 64 + mt * 16 + erow;
            float* p0 = C + (size_t)gr0 * Nld + n0 + lc;
            float* p1 = p0 + (size_t)8 * Nld;
            float2 v0, v1;
            v0.x = fmaxf(fmaf(acc[mt][nt][0], a0, b0), 0.0f);
            v0.y = fmaxf(fmaf(acc[mt][nt][1], a1, b1), 0.0f);
            v1.x = fmaxf(fmaf(acc[mt][nt][2], a0, b0), 0.0f);
            v1.y = fmaxf(fmaf(acc[mt][nt][3], a1, b1), 0.0f);
            if (addmode) {
                float2 o0 = *(float2*)p0;
                float2 o1 = *(float2*)p1;
                v0.x += o0.x; v0.y += o0.y;
                v1.x += o1.x; v1.y += o1.y;
            }
            *(float2*)p0 = v0;
            *(float2*)p1 = v1;
        }
    }
}

__global__ __launch_bounds__(256, 2)
void hmma_gemm4(const float* __restrict__ rgb, const float* __restrict__ depth,
                const float* __restrict__ mmwave, const float* __restrict__ lidar,
                const float* __restrict__ conv_b,
                const float* __restrict__ bn_g, const float* __restrict__ bn_b,
                const float* __restrict__ bn_m, const float* __restrict__ bn_v)
{
    const int y = blockIdx.y;
    int z, yl;
    if (y < 98)       { z = 0; yl = y; }
    else if (y < 196) { z = 1; yl = y - 98; }
    else if (y < 260) { z = 2; yl = y - 196; }
    else              { z = 3; yl = y - 260; }
    const float* A = (z == 0) ? rgb : (z == 1) ? depth : (z == 2) ? mmwave : lidar;
    const size_t Hoff = (z == 0) ? (size_t)OFF_RGB : (z == 1) ? (size_t)OFF_DEPTH
                      : (z == 2) ? (size_t)OFF_MM : (size_t)OFF_LIDAR;
    gemm_core_w<0>(A, g_wh + (size_t)z * 262144, g_wl + (size_t)z * 262144,
                   g_H + Hoff, 512, 512,
                   conv_b + z * 512, bn_g + z * 512, bn_b + z * 512,
                   bn_m + z * 512, bn_v + z * 512, 0,
                   yl * 128, blockIdx.x * 128);
}

// pe2 (fused pe1 A-gen) -> writes relu term to g_pe (no add)
__global__ __launch_bounds__(256, 2)
void hmma_pe2(const float* __restrict__ bias,
              const float* __restrict__ bng, const float* __restrict__ bnb,
              const float* __restrict__ bnm, const float* __restrict__ bnv)
{
    gemm_core_w<1>(nullptr, g_wh + W_PE2_OFF, g_wl + W_PE2_OFF,
                   g_pe, 512, 128, bias, bng, bnb, bnm, bnv, 0,
                   blockIdx.y * 128, blockIdx.x * 128);
}

// ---------------- H row lookup (concat order rgb|depth|mmwave|lidar) ----------------
__device__ __forceinline__ const float* h_row(int lcat, int b, int n0) {
    if (lcat < 49)  return g_H + OFF_RGB   + ((size_t)b * 49 + lcat) * 512 + n0;
    if (lcat < 98)  return g_H + OFF_DEPTH + ((size_t)b * 49 + (lcat - 49)) * 512 + n0;
    if (lcat < 130) return g_H + OFF_MM    + ((size_t)b * 32 + (lcat - 98)) * 512 + n0;
    if (lcat < 162) return g_H + OFF_LIDAR + ((size_t)b * 32 + (lcat - 130)) * 512 + n0;
    return nullptr;
}

// ---------------- transpose: H[b,l,o] -> Ht[b,o,l192] bf16 hi/lo ----------------
// grid (4 otile, 6 lchunk, 256 b), block 256
__global__ void tp_kernel()
{
    __shared__ unsigned short sH[128 * 34];
    __shared__ unsigned short sL[128 * 34];
    const int tid = threadIdx.x;
    const int obase = blockIdx.x * 128;
    const int lbase = blockIdx.y * 32;
    const int b = blockIdx.z;

    {
        const int o = tid & 127;
        const int half = tid >> 7;
#pragma unroll
        for (int i = 0; i < 16; i++) {
            const int lr = half * 16 + i;
            const float* row = h_row(lbase + lr, b, obase);
            float v = row ? row[o] : 0.0f;
            __nv_bfloat16 h = __float2bfloat16(v);
            __nv_bfloat16 l = __float2bfloat16(v - __bfloat162float(h));
            sH[o * 34 + lr] = __bfloat16_as_ushort(h);
            sL[o * 34 + lr] = __bfloat16_as_ushort(l);
        }
    }
    __syncthreads();
    {
        const int li = tid & 15;
#pragma unroll
        for (int p = 0; p < 8; p++) {
            const int o = p * 16 + (tid >> 4);
            const size_t rowoff = ((size_t)b * 512 + obase + o) * 192 + lbase;
            uint32_t vh = (uint32_t)sH[o * 34 + 2 * li] | ((uint32_t)sH[o * 34 + 2 * li + 1] << 16);
            uint32_t vl = (uint32_t)sL[o * 34 + 2 * li] | ((uint32_t)sL[o * 34 + 2 * li + 1] << 16);
            ((uint32_t*)(g_hth + rowoff))[li] = vh;
            ((uint32_t*)(g_htl + rowoff))[li] = vl;
        }
    }
}

// ---------------- mix GEMM: out = relu(Wblk @ Hcat + lb) + g_pe ----------------
// C rows = k (128), cols = o. A = Wblk[128,192] presplit, B = Ht[b, o, l] presplit.
__global__ __launch_bounds__(256, 1)
void mix_gemm(float* __restrict__ out)
{
    extern __shared__ char smem[];   // A st0 32K | A st1 32K | B st0 32K | B st1 32K
    __shared__ float s_rb[128];

    const int tid = threadIdx.x;
    const int wid = tid >> 5;
    const int lane = tid & 31;
    const int warp_m = wid >> 2;
    const int warp_n = wid & 3;
    const int n0 = blockIdx.x * 128;
    const int b  = blockIdx.y;

    if (tid < 128) s_rb[tid] = g_mlb[tid];

    float acc[4][4][4];
#pragma unroll
    for (int i = 0; i < 4; i++)
#pragma unroll
        for (int j = 0; j < 4; j++)
#pragma unroll
            for (int q = 0; q < 4; q++) acc[i][j][q] = 0.0f;

    const int g = tid & 7;
    const int r0 = tid >> 3;
    const uint32_t sb0 = smem_u32(smem);

#define MIX_ISSUE(ck) do {                                                    \
        const int k0 = (ck) << 6;                                             \
        const uint32_t as = sb0 + (uint32_t)(((ck) & 1) << 15);               \
        const uint32_t bs = sb0 + 65536u + (uint32_t)(((ck) & 1) << 15);      \
        _Pragma("unroll")                                                     \
        for (int pass = 0; pass < 4; pass++) {                                \
            const int r = r0 + 32 * pass;                                     \
            const uint32_t off = (uint32_t)(r * 128 + ((g ^ (r & 7)) << 4));  \
            const size_t aoff = (size_t)r * 192 + k0 + g * 8;                 \
            cp16(as + off, g_mwh + aoff);                                     \
            cp16(as + TILE_BYTES + off, g_mwl + aoff);                        \
            const size_t boff = ((size_t)b * 512 + n0 + r) * 192 + k0 + g * 8;\
            cp16(bs + off, g_hth + boff);                                     \
            cp16(bs + TILE_BYTES + off, g_htl + boff);                        \
        }                                                                     \
        CP_COMMIT();                                                          \
    } while (0)

    MIX_ISSUE(0);
    MIX_ISSUE(1);

    for (int ck = 0; ck < 3; ck++) {
        if (ck == 2) { CP_WAIT0(); } else { CP_WAIT1(); }
        __syncthreads();

        {
            const uint32_t abase = sb0 + (uint32_t)((ck & 1) << 15);
            const uint32_t bbase = sb0 + 65536u + (uint32_t)((ck & 1) << 15);
            const int arow = warp_m * 64 + (lane & 15);
            const int ahalf = lane >> 4;
            const int bn_ = warp_n * 32 + (lane & 7);
            const int bhalf = (lane >> 3) & 1;
#pragma unroll
            for (int kb = 0; kb < 4; kb++) {
                uint32_t aH[4][4], aL[4][4], bH[4][2], bL[4][2];
#pragma unroll
                for (int mt = 0; mt < 4; mt++) {
                    const int r = arow + mt * 16;
                    const uint32_t chunk = (uint32_t)((2 * kb + ahalf) ^ (r & 7));
                    const uint32_t ad = abase + (uint32_t)(r * 128) + chunk * 16;
                    LDSM_X4(aH[mt][0], aH[mt][1], aH[mt][2], aH[mt][3], ad);
                    LDSM_X4(aL[mt][0], aL[mt][1], aL[mt][2], aL[mt][3], ad + TILE_BYTES);
                }
#pragma unroll
                for (int nt = 0; nt < 4; nt++) {
                    const int n = bn_ + nt * 8;
                    const uint32_t chunk = (uint32_t)((2 * kb + bhalf) ^ (n & 7));
                    const uint32_t bd = bbase + (uint32_t)(n * 128) + chunk * 16;
                    LDSM_X2(bH[nt][0], bH[nt][1], bd);
                    LDSM_X2(bL[nt][0], bL[nt][1], bd + TILE_BYTES);
                }
#pragma unroll
                for (int mt = 0; mt < 4; mt++)
#pragma unroll
                    for (int nt = 0; nt < 4; nt++) {
                        mma_bf16(acc[mt][nt], aH[mt], bH[nt]);
                        mma_bf16(acc[mt][nt], aH[mt], bL[nt]);
                        mma_bf16(acc[mt][nt], aL[mt], bH[nt]);
                    }
            }
        }
        __syncthreads();
        if (ck == 0) MIX_ISSUE(2);
    }
#undef MIX_ISSUE

    // epilogue: out = relu(acc + rowbias) + g_pe
    const int erow = (lane >> 2);
    const int ecol = 2 * (lane & 3);
#pragma unroll
    for (int mt = 0; mt < 4; mt++) {
        const int row = warp_m * 64 + mt * 16 + erow;
        const float rb0 = s_rb[row];
        const float rb1 = s_rb[row + 8];
#pragma unroll
        for (int nt = 0; nt < 4; nt++) {
            const int lc = warp_n * 32 + nt * 8 + ecol;
            const size_t base0 = ((size_t)b * 128 + row) * 512 + n0 + lc;
            const size_t base1 = base0 + (size_t)8 * 512;
            float2 p0 = *(const float2*)(g_pe + base0);
            float2 p1 = *(const float2*)(g_pe + base1);
            float2 v0, v1;
            v0.x = fmaxf(acc[mt][nt][0] + rb0, 0.0f) + p0.x;
            v0.y = fmaxf(acc[mt][nt][1] + rb0, 0.0f) + p0.y;
            v1.x = fmaxf(acc[mt][nt][2] + rb1, 0.0f) + p1.x;
            v1.y = fmaxf(acc[mt][nt][3] + rb1, 0.0f) + p1.y;
            *(float2*)(out + base0) = v0;
            *(float2*)(out + base1) = v1;
        }
    }
}

// ---------------- prep ----------------
__global__ void prep_kernel(const float* __restrict__ conv_w, const float* __restrict__ pe_w2,
                            const float* __restrict__ pe_w1, const float* __restrict__ pe_b1,
                            const float* __restrict__ pe_g1, const float* __restrict__ pe_bb1,
                            const float* __restrict__ pe_m1, const float* __restrict__ pe_v1,
                            const float* __restrict__ lin_w_img, const float* __restrict__ lin_b_img,
                            const float* __restrict__ lin_w_pc,  const float* __restrict__ lin_b_pc)
{
    int idx = blockIdx.x * 256 + threadIdx.x;
    if (idx < W_TOTAL) {
        float v = (idx < W_PE2_OFF) ? conv_w[idx] : pe_w2[idx - W_PE2_OFF];
        __nv_bfloat16 h = __float2bfloat16(v);
        g_wh[idx] = h;
        g_wl[idx] = __float2bfloat16(v - __bfloat162float(h));
    }
    if (idx < 128 * 192) {
        const int krow = idx / 192, lcat = idx % 192;
        const int mod = krow >> 5, k = krow & 31;
        float w = 0.0f;
        if (mod == 0)      { if (lcat < 49)                 w = lin_w_img[k * 49 + lcat]; }
        else if (mod == 1) { if (lcat >= 49 && lcat < 98)   w = lin_w_img[(32 + k) * 49 + lcat - 49]; }
        else if (mod == 2) { if (lcat >= 98 && lcat < 130)  w = lin_w_pc[k * 32 + lcat - 98]; }
        else               { if (lcat >= 130 && lcat < 162) w = lin_w_pc[(32 + k) * 32 + lcat - 130]; }
        __nv_bfloat16 h = __float2bfloat16(w);
        g_mwh[idx] = h;
        g_mwl[idx] = __float2bfloat16(w - __bfloat162float(h));
    }
    if (idx < 128) {
        const int mod = idx >> 5, k = idx & 31;
        g_mlb[idx] = (mod == 0) ? lin_b_img[k] : (mod == 1) ? lin_b_img[32 + k]
                   : (mod == 2) ? lin_b_pc[k] : lin_b_pc[32 + k];
        float s = pe_g1[idx] * rsqrtf(pe_v1[idx] + EPS_BN);
        g_peA[idx * 4 + 0] = pe_w1[idx * 3 + 0] * s;
        g_peA[idx * 4 + 1] = pe_w1[idx * 3 + 1] * s;
        g_peA[idx * 4 + 2] = pe_w1[idx * 3 + 2] * s;
        g_peA[idx * 4 + 3] = (pe_b1[idx] - pe_m1[idx]) * s + pe_bb1[idx];
    }
}

// ---------------- threefry-2x32 ----------------
__device__ __forceinline__ unsigned rotl32(unsigned x, int d) {
    return (x << d) | (x >> (32 - d));
}
#define TF_ROUND(x0, x1, r) do { x0 += x1; x1 = rotl32(x1, r); x1 ^= x0; } while (0)
__device__ __forceinline__ void threefry2x32(unsigned k0, unsigned k1,
                                             unsigned& x0, unsigned& x1) {
    const unsigned kx = 0x1BD11BDAu ^ k0 ^ k1;
    x0 += k0; x1 += k1;
    TF_ROUND(x0, x1, 13); TF_ROUND(x0, x1, 15); TF_ROUND(x0, x1, 26); TF_ROUND(x0, x1, 6);
    x0 += k1; x1 += kx + 1u;
    TF_ROUND(x0, x1, 17); TF_ROUND(x0, x1, 29); TF_ROUND(x0, x1, 16); TF_ROUND(x0, x1, 24);
    x0 += kx; x1 += k0 + 2u;
    TF_ROUND(x0, x1, 13); TF_ROUND(x0, x1, 15); TF_ROUND(x0, x1, 26); TF_ROUND(x0, x1, 6);
    x0 += k0; x1 += k1 + 3u;
    TF_ROUND(x0, x1, 17); TF_ROUND(x0, x1, 29); TF_ROUND(x0, x1, 16); TF_ROUND(x0, x1, 24);
    x0 += k1; x1 += kx + 4u;
    TF_ROUND(x0, x1, 13); TF_ROUND(x0, x1, 15); TF_ROUND(x0, x1, 26); TF_ROUND(x0, x1, 6);
    x0 += kx; x1 += k0 + 5u;
}
__device__ __forceinline__ uint32_t redux_max_u32(uint32_t v) {
    uint32_t r;
    asm("redux.sync.max.u32 %0, %1, 0xffffffff;" : "=r"(r) : "r"(v));
    return r;
}
__device__ __forceinline__ uint32_t redux_min_u32(uint32_t v) {
    uint32_t r;
    asm("redux.sync.min.u32 %0, %1, 0xffffffff;" : "=r"(r) : "r"(v));
    return r;
}

// ---------------- FPS ----------------
__global__ __launch_bounds__(512)
void fps_kernel(const float* __restrict__ pts, float* __restrict__ nxyz) {
    extern __shared__ float sh[];
    float* xs = sh;
    float* ys = sh + 4096;
    float* zs = sh + 8192;
    __shared__ uint32_t red_v[16];
    __shared__ uint32_t red_i[16];
    __shared__ int sm_far;

    const int b = blockIdx.x;
    const int tid = threadIdx.x;
    const int lane = tid & 31;
    const int warp = tid >> 5;
    const float* p = pts + (size_t)b * 4096 * 3;
    for (int i = tid; i < 4096; i += 512) {
        xs[i] = p[3 * i + 0];
        ys[i] = p[3 * i + 1];
        zs[i] = p[3 * i + 2];
    }
    if (tid == 0) {
        unsigned a0 = 0u, a1 = 1u;
        threefry2x32(0u, 42u, a0, a1);
        unsigned c0 = 0u, c1 = (unsigned)b;
        threefry2x32(a0, a1, c0, c1);
        sm_far = (int)((c0 ^ c1) & 4095u);
    }
    __syncthreads();

    float dist[8];
#pragma unroll
    for (int j = 0; j < 8; j++) dist[j] = 1e10f;

    float* outp = nxyz + (size_t)b * 128 * 3;
    for (int it = 0; it < 128; ++it) {
        const int far = sm_far;
        const float cx = xs[far], cy = ys[far], cz = zs[far];
        if (tid == 0) {
            outp[3 * it + 0] = cx;
            outp[3 * it + 1] = cy;
            outp[3 * it + 2] = cz;
        }
        float bv = -1.0f;
        int bi = 0;
#pragma unroll
        for (int j = 0; j < 8; j++) {
            const int pi = (j << 9) + tid;
            float dx = __fadd_rn(xs[pi], -cx);
            float dy = __fadd_rn(ys[pi], -cy);
            float dz = __fadd_rn(zs[pi], -cz);
            float s0 = __fmul_rn(dx, dx);
            float s1 = __fmul_rn(dy, dy);
            float s2 = __fmul_rn(dz, dz);
            float d  = __fadd_rn(__fadd_rn(s0, s1), s2);
            float nd = fminf(dist[j], d);
            dist[j] = nd;
            if (nd > bv) { bv = nd; bi = pi; }
        }
        uint32_t bvu = __float_as_uint(bv);
        uint32_t gv = redux_max_u32(bvu);
        uint32_t cand = (bvu == gv) ? (uint32_t)bi : 0xFFFFFFFFu;
        uint32_t gi = redux_min_u32(cand);
        if (lane == 0) { red_v[warp] = gv; red_i[warp] = gi; }
        __syncthreads();
        if (tid < 32) {
            uint32_t v = (lane < 16) ? red_v[lane] : 0u;
            uint32_t i = (lane < 16) ? red_i[lane] : 0xFFFFFFFFu;
            uint32_t gv2 = redux_max_u32(v);
            uint32_t cand2 = (v == gv2) ? i : 0xFFFFFFFFu;
            uint32_t gi2 = redux_min_u32(cand2);
            if (lane == 0) sm_far = (int)gi2;
        }
        __syncthreads();
    }
}

// ---------------- launch ----------------
extern "C" void kernel_launch(void* const* d_in, const int* in_sizes, int n_in,
                              void* d_out, int out_size) {
    (void)in_sizes; (void)n_in; (void)out_size;
    const float* rgb       = (const float*)d_in[0];
    const float* depth     = (const float*)d_in[1];
    const float* mmwave    = (const float*)d_in[2];
    const float* lidar     = (const float*)d_in[3];
    const float* pts       = (const float*)d_in[4];
    const float* conv_w    = (const float*)d_in[5];
    const float* conv_b    = (const float*)d_in[6];
    const float* bn_g      = (const float*)d_in[7];
    const float* bn_b      = (const float*)d_in[8];
    const float* bn_m      = (const float*)d_in[9];
    const float* bn_v      = (const float*)d_in[10];
    const float* lin_w_img = (const float*)d_in[11];
    const float* lin_b_img = (const float*)d_in[12];
    const float* lin_w_pc  = (const float*)d_in[13];
    const float* lin_b_pc  = (const float*)d_in[14];
    const float* pe_w1     = (const float*)d_in[15];
    const float* pe_b1     = (const float*)d_in[16];
    const float* pe_g1     = (const float*)d_in[17];
    const float* pe_bb1    = (const float*)d_in[18];
    const float* pe_m1     = (const float*)d_in[19];
    const float* pe_v1     = (const float*)d_in[20];
    const float* pe_w2     = (const float*)d_in[21];
    const float* pe_b2     = (const float*)d_in[22];
    const float* pe_g2     = (const float*)d_in[23];
    const float* pe_bb2    = (const float*)d_in[24];
    const float* pe_m2     = (const float*)d_in[25];
    const float* pe_v2     = (const float*)d_in[26];
    float* out = (float*)d_out;

    float* nx;
    cudaGetSymbolAddress((void**)&nx, g_newxyz);

    static cudaStream_t s2 = nullptr;
    static cudaEvent_t evA = nullptr, evP = nullptr, evB = nullptr;
    if (!s2) {
        cudaStreamCreateWithFlags(&s2, cudaStreamNonBlocking);
        cudaEventCreateWithFlags(&evA, cudaEventDisableTiming);
        cudaEventCreateWithFlags(&evP, cudaEventDisableTiming);
        cudaEventCreateWithFlags(&evB, cudaEventDisableTiming);
        cudaFuncSetAttribute(fps_kernel, cudaFuncAttributeMaxDynamicSharedMemorySize, 50176);
        cudaFuncSetAttribute(hmma_gemm4, cudaFuncAttributeMaxDynamicSharedMemorySize, GEMM_SMEM);
        cudaFuncSetAttribute(hmma_pe2, cudaFuncAttributeMaxDynamicSharedMemorySize, GEMM_SMEM);
        cudaFuncSetAttribute(mix_gemm, cudaFuncAttributeMaxDynamicSharedMemorySize, MIX_SMEM);
    }

    // fork: FPS on side stream
    cudaEventRecord(evA, 0);
    cudaStreamWaitEvent(s2, evA, 0);
    fps_kernel<<<256, 512, 49152, s2>>>(pts, nx);

    // main: prep (weights + pe1 fold + Wblk)
    prep_kernel<<<(W_TOTAL + 255) / 256, 256>>>(conv_w, pe_w2, pe_w1, pe_b1,
                                                pe_g1, pe_bb1, pe_m1, pe_v1,
                                                lin_w_img, lin_b_img, lin_w_pc, lin_b_pc);
    cudaEventRecord(evP, 0);

    // side stream: pe2 (needs FPS + prep) -> g_pe, concurrent with gemm4
    cudaStreamWaitEvent(s2, evP, 0);
    hmma_pe2<<<dim3(4, 256), 256, GEMM_SMEM, s2>>>(pe_b2, pe_g2, pe_bb2, pe_m2, pe_v2);
    cudaEventRecord(evB, s2);

    // main: branch GEMMs -> transpose -> mix (+pe add fused)
    hmma_gemm4<<<dim3(4, 324), 256, GEMM_SMEM>>>(rgb, depth, mmwave, lidar,
        conv_b, bn_g, bn_b, bn_m, bn_v);
    tp_kernel<<<dim3(4, 6, 256), 256>>>();
    cudaStreamWaitEvent(0, evB, 0);
    mix_gemm<<<dim3(4, 256), 256, MIX_SMEM>>>(out);
}